// round 12
// baseline (speedup 1.0000x reference)
#include <cuda_runtime.h>
#include <cuda_bf16.h>
#include <math.h>

#define BB 16
#define LL 4096
#define DM 64
#define DI 128
#define DS 32
#define NH 2
#define HD 64
#define CDIM 192
#define DPJ 322
#define ZST 328
#define NT (BB*LL)
#define NLAYER 8
#define CH 32
#define SEG 32
#define SLEN (LL/SEG)    // 128
#define NPAD 384
#define NS 328
#define KP 72
#define KP2 136
#define RSTR 132
#define NF4 (NPAD*4)     // fragment entries per part per layer
#define NS4 (NS*4)

// ---------------- device scratch ----------------
__device__ float g_zx[(size_t)NT*ZST];
__device__ float g_y [(size_t)NT*DI];
__device__ float g_Cx[(size_t)NT*NH*DS];
__device__ float g_S  [32*SEG*2048];
__device__ float g_H0 [32*SEG*2048];
__device__ float g_D  [32*SEG];
__device__ ulonglong2 g_Wf[(size_t)NLAYER*4*NF4];        // fragment-ready Win: [l][part][n*4+tg]
__device__ __nv_bfloat16 g_Woh[(size_t)NLAYER*64*128];
__device__ __nv_bfloat16 g_Wol[(size_t)NLAYER*64*128];

// ---------------- f32x2 packed helpers ----------------
__device__ __forceinline__ unsigned long long pk2(float lo, float hi){
    unsigned long long r; asm("mov.b64 %0,{%1,%2};" : "=l"(r) : "f"(lo), "f"(hi)); return r;
}
__device__ __forceinline__ void upk2(unsigned long long v, float& lo, float& hi){
    asm("mov.b64 {%0,%1},%2;" : "=f"(lo), "=f"(hi) : "l"(v));
}
__device__ __forceinline__ unsigned long long mul2(unsigned long long a, unsigned long long b){
    unsigned long long d; asm("mul.rn.f32x2 %0,%1,%2;" : "=l"(d) : "l"(a), "l"(b)); return d;
}
__device__ __forceinline__ unsigned long long fma2(unsigned long long a, unsigned long long b, unsigned long long c){
    unsigned long long d; asm("fma.rn.f32x2 %0,%1,%2,%3;" : "=l"(d) : "l"(a), "l"(b), "l"(c)); return d;
}

// ---------------- bf16 helpers ----------------
__device__ __forceinline__ unsigned pkbf(float x, float y){
    __nv_bfloat162 t = __floats2bfloat162_rn(x, y);
    return *(unsigned*)&t;
}
__device__ __forceinline__ float bfres(float x){
    return x - __bfloat162float(__float2bfloat16_rn(x));
}
__device__ __forceinline__ void mma16816(float* c, const unsigned* a, const unsigned* b){
    asm volatile("mma.sync.aligned.m16n8k16.row.col.f32.bf16.bf16.f32 "
                 "{%0,%1,%2,%3}, {%4,%5,%6,%7}, {%8,%9}, {%0,%1,%2,%3};"
                 : "+f"(c[0]), "+f"(c[1]), "+f"(c[2]), "+f"(c[3])
                 : "r"(a[0]), "r"(a[1]), "r"(a[2]), "r"(a[3]), "r"(b[0]), "r"(b[1]));
}

// ---------------- cp.async helpers ----------------
__device__ __forceinline__ void cpa16(void* s, const void* g){
    unsigned a = (unsigned)__cvta_generic_to_shared(s);
    asm volatile("cp.async.ca.shared.global [%0], [%1], 16;" :: "r"(a), "l"(g));
}
__device__ __forceinline__ void cpa4(void* s, const void* g){
    unsigned a = (unsigned)__cvta_generic_to_shared(s);
    asm volatile("cp.async.ca.shared.global [%0], [%1], 4;" :: "r"(a), "l"(g));
}

// ---------------- kernel 0: weight prep ----------------
// g_Wf layout: part 0 = hi(k offset 0), 1 = hi(+8), 2 = lo(0), 3 = lo(+8);
// entry [n*4+tg] = 4x unsigned, one per ks: pair (B[n][ks*16+tg*2+off], B[n][...+1])
__global__ __launch_bounds__(256) void k_prep(const float* __restrict__ Win, const float* __restrict__ Wout)
{
    int i = blockIdx.x * 256 + threadIdx.x;
    const int NFT = NLAYER*4*NF4;
    const int NO  = NLAYER*64*128;
    if (i < NFT){
        int l = i / (4*NF4);
        int rem = i - l*(4*NF4);
        int part = rem / NF4;
        int idx = rem - part*NF4;
        int n = idx >> 2, tg = idx & 3;
        int off = (part & 1) * 8;
        bool isHi = part < 2;
        const float* W = Win + (size_t)l*DM*DPJ;
        unsigned vals[4];
        #pragma unroll
        for (int ks = 0; ks < 4; ks++){
            int k = ks*16 + tg*2 + off;
            float w0 = (n < DPJ) ? W[k*DPJ + n]     : 0.0f;
            float w1 = (n < DPJ) ? W[(k+1)*DPJ + n] : 0.0f;
            vals[ks] = isHi ? pkbf(w0, w1) : pkbf(bfres(w0), bfres(w1));
        }
        ulonglong2 v;
        v.x = (unsigned long long)vals[0] | ((unsigned long long)vals[1] << 32);
        v.y = (unsigned long long)vals[2] | ((unsigned long long)vals[3] << 32);
        g_Wf[i] = v;
    } else if (i < NFT + NO){
        int j = i - NFT;
        int l = j / (64*128);
        int r = j - l*(64*128);
        int n = r >> 7, k = r & 127;
        float w = Wout[(size_t)l*DI*DM + k*DM + n];
        __nv_bfloat16 hi = __float2bfloat16_rn(w);
        g_Woh[j] = hi;
        g_Wol[j] = __float2bfloat16_rn(w - __bfloat162float(hi));
    }
}

// ---------------- GEMM2 core: zx[128 x 322] = A(smem hi/lo, KP stride) @ Win(fragment smem) ----
__device__ __forceinline__ void gemm2_core(const __nv_bfloat16* Ah, const __nv_bfloat16* Al,
                                           const ulonglong2* Bfr, size_t rowBase, int tid)
{
    int w = tid >> 5, lane = tid & 31;
    int g = lane >> 2, tg = lane & 3;
    int r0 = (w & 3) * 32;
    int ntB = (w >> 2) ? 21 : 0;
    int ntE = (w >> 2) ? 41 : 21;

    unsigned ah[2][4][4], al[2][4][4];
    #pragma unroll
    for (int mt = 0; mt < 2; mt++)
        #pragma unroll
        for (int ks = 0; ks < 4; ks++){
            int c0 = ks*16 + tg*2;
            int mr = r0 + mt*16 + g;
            ah[mt][ks][0] = *(const unsigned*)&Ah[mr*KP + c0];
            ah[mt][ks][1] = *(const unsigned*)&Ah[(mr+8)*KP + c0];
            ah[mt][ks][2] = *(const unsigned*)&Ah[mr*KP + c0 + 8];
            ah[mt][ks][3] = *(const unsigned*)&Ah[(mr+8)*KP + c0 + 8];
            al[mt][ks][0] = *(const unsigned*)&Al[mr*KP + c0];
            al[mt][ks][1] = *(const unsigned*)&Al[(mr+8)*KP + c0];
            al[mt][ks][2] = *(const unsigned*)&Al[mr*KP + c0 + 8];
            al[mt][ks][3] = *(const unsigned*)&Al[(mr+8)*KP + c0 + 8];
        }

    #pragma unroll 1
    for (int nt = ntB; nt < ntE; nt++){
        ulonglong2 h0 = Bfr[0*NS4 + nt*32 + lane];
        ulonglong2 h1 = Bfr[1*NS4 + nt*32 + lane];
        ulonglong2 l0 = Bfr[2*NS4 + nt*32 + lane];
        ulonglong2 l1 = Bfr[3*NS4 + nt*32 + lane];
        const unsigned* ph0 = (const unsigned*)&h0;
        const unsigned* ph1 = (const unsigned*)&h1;
        const unsigned* pl0 = (const unsigned*)&l0;
        const unsigned* pl1 = (const unsigned*)&l1;
        unsigned bh[4][2], bl[4][2];
        #pragma unroll
        for (int ks = 0; ks < 4; ks++){
            bh[ks][0] = ph0[ks]; bh[ks][1] = ph1[ks];
            bl[ks][0] = pl0[ks]; bl[ks][1] = pl1[ks];
        }
        int col = nt*8 + tg*2;
        #pragma unroll
        for (int mt = 0; mt < 2; mt++){
            float acc[4] = {0.f, 0.f, 0.f, 0.f};
            #pragma unroll
            for (int ks = 0; ks < 4; ks++) mma16816(acc, ah[mt][ks], bh[ks]);
            #pragma unroll
            for (int ks = 0; ks < 4; ks++) mma16816(acc, ah[mt][ks], bl[ks]);
            #pragma unroll
            for (int ks = 0; ks < 4; ks++) mma16816(acc, al[mt][ks], bh[ks]);
            if (col < DPJ){
                size_t rr = rowBase + r0 + mt*16 + g;
                *(float2*)&g_zx[rr*ZST + col]       = make_float2(acc[0], acc[1]);
                *(float2*)&g_zx[(rr + 8)*ZST + col] = make_float2(acc[2], acc[3]);
            }
        }
    }
}

// ---------------- kernel 1: layer-0 in-projection via mma.sync ----------------
__global__ __launch_bounds__(256) void k_inproj_mma(const float* __restrict__ xin, int layer)
{
    extern __shared__ __align__(16) char sm[];
    __nv_bfloat16* Ah = (__nv_bfloat16*)sm;       // 128*KP
    __nv_bfloat16* Al = Ah + 128*KP;
    ulonglong2* Bfr = (ulonglong2*)(sm + 36864);  // [4][NS4]
    int tid = threadIdx.x;
    size_t rowBase = (size_t)blockIdx.x << 7;

    for (int i = tid; i < 128*32; i += 256){
        int m = i >> 5, kp = (i & 31) << 1;
        float2 v = *(const float2*)&xin[(rowBase + m)*DM + kp];
        *(unsigned*)&Ah[m*KP + kp] = pkbf(v.x, v.y);
        *(unsigned*)&Al[m*KP + kp] = pkbf(bfres(v.x), bfres(v.y));
    }
    {
        const ulonglong2* src = g_Wf + (size_t)layer*4*NF4;
        for (int i = tid; i < 4*NS4; i += 256){
            int part = i / NS4, idx = i - part*NS4;
            Bfr[part*NS4 + idx] = src[part*NF4 + idx];
        }
    }
    __syncthreads();
    gemm2_core(Ah, Al, Bfr, rowBase, tid);
}

// ---------------- kernel 2: fused conv + SiLU + dt/dA + forward scan (local) ----------------
__global__ __launch_bounds__(256) void k_scanf(const float* __restrict__ cw, const float* __restrict__ cb,
                                               const float* __restrict__ dtb, const float* __restrict__ Alog,
                                               const float* __restrict__ Dpw)
{
    extern __shared__ __align__(16) float sf[];
    float* raw   = sf;                    // [2][35][RSTR]
    float* convx = sf + 2*35*RSTR;        // [32][64]
    float* Bs    = convx + 32*64;         // [32][32]
    float* Cs    = Bs + 32*32;            // [32][32]
    float* dts   = Cs + 32*32;            // [32]
    float* dAs   = dts + 32;              // [32]

    int bid = blockIdx.x;
    int bh = bid >> 5, seg = bid & 31;
    int b = bh >> 1, hh = bh & 1;
    int tid = threadIdx.x;
    int p = tid >> 2, q = tid & 3;
    size_t base = (size_t)b*LL + (size_t)seg*SLEN;
    float dp = Dpw[hh];
    float Acoef = -expf(Alog[hh]);
    float dtbv = dtb[hh];

    int cch = tid & 127;
    int gch = (cch < 64) ? (hh*64 + cch) : (cch < 96 ? (128 + cch - 64) : (160 + cch - 96));
    float w0 = cw[gch*4+0], w1 = cw[gch*4+1], w2 = cw[gch*4+2], w3 = cw[gch*4+3];
    float cbv = cb[gch];

    auto stage = [&](int bufi, int t0){
        float* rb = raw + bufi*35*RSTR;
        for (int i = tid; i < 1152; i += 256){
            if (i < 1120){
                int row = i >> 5, j = i & 31;
                int fo = j << 2;
                int t = t0 - 3 + row;
                if (seg == 0 && t < 0){
                    *(float4*)&rb[row*RSTR + fo] = make_float4(0.f,0.f,0.f,0.f);
                } else {
                    size_t bt = base + t;
                    int col = (fo < 64) ? (128 + hh*64 + fo) : (fo < 96 ? (256 + fo - 64) : (288 + fo - 96));
                    cpa16(&rb[row*RSTR + fo], &g_zx[bt*ZST + col]);
                }
            } else {
                int r = 3 + (i - 1120);
                size_t bt = base + t0 - 3 + r;
                cpa4(&rb[r*RSTR + 128], &g_zx[bt*ZST + 320 + hh]);
            }
        }
        asm volatile("cp.async.commit_group;");
    };

    unsigned long long hs2[4];
    #pragma unroll
    for (int i = 0; i < 4; i++) hs2[i] = pk2(0.f, 0.f);
    float dprod = 1.f;

    stage(0, 0);
    int buf = 0;
    for (int c0 = 0; c0 < SLEN/CH; c0++){
        if (c0 + 1 < SLEN/CH){
            stage(buf^1, (c0+1)*CH);
            asm volatile("cp.async.wait_group 1;");
        } else {
            asm volatile("cp.async.wait_group 0;");
        }
        __syncthreads();

        {
            float* rb = raw + buf*35*RSTR;
            int half = tid >> 7;
            float* outp; int ostr; int oc;
            if (cch < 64)      { outp = convx; ostr = 64; oc = cch; }
            else if (cch < 96) { outp = Bs;    ostr = 32; oc = cch - 64; }
            else               { outp = Cs;    ostr = 32; oc = cch - 96; }
            #pragma unroll
            for (int k = 0; k < 16; k++){
                int tt = half*16 + k;
                float acc = cbv + w0*rb[tt*RSTR + cch] + w1*rb[(tt+1)*RSTR + cch]
                                + w2*rb[(tt+2)*RSTR + cch] + w3*rb[(tt+3)*RSTR + cch];
                float s = acc / (1.0f + __expf(-acc));
                outp[tt*ostr + oc] = s;
            }
            if (tid < 32){
                float rdt = rb[(3+tid)*RSTR + 128] + dtbv;
                float dt = (rdt > 20.f) ? rdt : log1pf(expf(rdt));
                dts[tid] = dt;
                dAs[tid] = expf(dt * Acoef);
            }
        }
        __syncthreads();

        #pragma unroll 8
        for (int s = 0; s < CH; s++){
            float dAv = dAs[s], dtv = dts[s];
            float x = convx[s*64 + p];
            dprod *= dAv;
            float dx = dtv * x;
            unsigned long long dx2 = pk2(dx,dx), dA2 = pk2(dAv,dAv);
            const ulonglong2* bp = (const ulonglong2*)&Bs[s*32 + (q<<3)];
            ulonglong2 bA = bp[0], bB = bp[1];
            hs2[0] = fma2(hs2[0], dA2, mul2(dx2, bA.x));
            hs2[1] = fma2(hs2[1], dA2, mul2(dx2, bA.y));
            hs2[2] = fma2(hs2[2], dA2, mul2(dx2, bB.x));
            hs2[3] = fma2(hs2[3], dA2, mul2(dx2, bB.y));
            const ulonglong2* cp = (const ulonglong2*)&Cs[s*32 + (q<<3)];
            ulonglong2 cA = cp[0], cB = cp[1];
            unsigned long long acc2 = mul2(hs2[0], cA.x);
            acc2 = fma2(hs2[1], cA.y, acc2);
            acc2 = fma2(hs2[2], cB.x, acc2);
            acc2 = fma2(hs2[3], cB.y, acc2);
            float alo, ahi; upk2(acc2, alo, ahi);
            float acc = alo + ahi;
            acc += __shfl_xor_sync(0xffffffffu, acc, 1);
            acc += __shfl_xor_sync(0xffffffffu, acc, 2);
            if (q == 0){
                size_t gt = base + c0*CH + s;
                g_y[gt*DI + hh*HD + p] = acc + dp * x;
                if (p < 32) g_Cx[gt*(NH*DS) + hh*DS + p] = dprod * Cs[s*32 + p];
            }
        }
        __syncthreads();
        buf ^= 1;
    }

    float h[8];
    upk2(hs2[0], h[0], h[1]); upk2(hs2[1], h[2], h[3]);
    upk2(hs2[2], h[4], h[5]); upk2(hs2[3], h[6], h[7]);
    float* sp = &g_S[((size_t)bh*SEG + seg)*2048 + (p<<5) + (q<<3)];
    *(float4*)&sp[0] = make_float4(h[0],h[1],h[2],h[3]);
    *(float4*)&sp[4] = make_float4(h[4],h[5],h[6],h[7]);
    if (tid == 0) g_D[bh*SEG + seg] = dprod;
}

// ---------------- kernel 2b: h0 prefix over segments (per bh), depth-4 prefetch ----------------
__global__ __launch_bounds__(64) void k_hpre()
{
    __shared__ float Dsm[SEG];
    int bh = blockIdx.x >> 3, chunk = blockIdx.x & 7;
    int e0 = chunk*256 + threadIdx.x*4;
    if (threadIdx.x < SEG) Dsm[threadIdx.x] = g_D[bh*SEG + threadIdx.x];
    __syncthreads();
    const float* Sb = &g_S[(size_t)bh*SEG*2048 + e0];
    float*       Hb = &g_H0[(size_t)bh*SEG*2048 + e0];
    float4 buf[4];
    #pragma unroll
    for (int k = 0; k < 4; k++) buf[k] = *(const float4*)(Sb + (size_t)k*2048);
    float4 h = make_float4(0.f,0.f,0.f,0.f);
    #pragma unroll 4
    for (int s = 1; s < SEG; s++){
        float4 Sv = buf[(s-1)&3];
        if (s + 3 < SEG) buf[(s-1)&3] = *(const float4*)(Sb + (size_t)(s+3)*2048);
        float D = Dsm[s-1];
        h.x = D*h.x + Sv.x; h.y = D*h.y + Sv.y;
        h.z = D*h.z + Sv.z; h.w = D*h.w + Sv.w;
        *(float4*)(Hb + (size_t)s*2048) = h;
    }
}

// ---------------- kernel 3: cross-segment correction  y += Ccum @ h0^T ----------------
__global__ __launch_bounds__(256) void k_corr()
{
    __shared__ __align__(16) float Ccums[128*32];
    __shared__ __align__(16) float h0p[2048];
    __shared__ __align__(16) float h0sm[32*68];
    int bid = blockIdx.x;
    int bh = bid >> 5, seg = bid & 31;
    if (seg == 0) return;
    int b = bh >> 1, hh = bh & 1;
    int tid = threadIdx.x;
    size_t base = (size_t)b*LL + (size_t)seg*SLEN;

    {
        const float* src = &g_Cx[base*(NH*DS) + hh*DS];
        for (int i = tid; i < 1024; i += 256){
            int t = i >> 3, j = i & 7;
            cpa16(&Ccums[t*32 + j*4], src + (size_t)t*(NH*DS) + j*4);
        }
        const float* hsrc = &g_H0[((size_t)bh*SEG + seg)*2048];
        for (int i = tid; i < 512; i += 256)
            cpa16(&h0p[i*4], hsrc + i*4);
        asm volatile("cp.async.commit_group;");
    }
    asm volatile("cp.async.wait_group 0;");
    __syncthreads();

    {
        int e = tid*8;
        float4 a = *(float4*)&h0p[e], c = *(float4*)&h0p[e+4];
        int p = e >> 5, n0 = e & 31;
        h0sm[(n0+0)*68 + p] = a.x; h0sm[(n0+1)*68 + p] = a.y;
        h0sm[(n0+2)*68 + p] = a.z; h0sm[(n0+3)*68 + p] = a.w;
        h0sm[(n0+4)*68 + p] = c.x; h0sm[(n0+5)*68 + p] = c.y;
        h0sm[(n0+6)*68 + p] = c.z; h0sm[(n0+7)*68 + p] = c.w;
    }
    __syncthreads();

    int t0 = (tid >> 3) << 2;
    int p0 = (tid & 7) << 3;
    unsigned long long acc2[4][4];
    #pragma unroll
    for (int i = 0; i < 4; i++)
        #pragma unroll
        for (int j = 0; j < 4; j++) acc2[i][j] = pk2(0.f, 0.f);
    #pragma unroll 4
    for (int n = 0; n < 32; n++){
        const ulonglong2* hp = (const ulonglong2*)&h0sm[n*68 + p0];
        ulonglong2 ha = hp[0], hb = hp[1];
        #pragma unroll
        for (int i = 0; i < 4; i++){
            float cc = Ccums[(t0+i)*32 + n];
            unsigned long long c2 = pk2(cc, cc);
            acc2[i][0] = fma2(c2, ha.x, acc2[i][0]);
            acc2[i][1] = fma2(c2, ha.y, acc2[i][1]);
            acc2[i][2] = fma2(c2, hb.x, acc2[i][2]);
            acc2[i][3] = fma2(c2, hb.y, acc2[i][3]);
        }
    }
    #pragma unroll
    for (int i = 0; i < 4; i++){
        size_t gt = base + t0 + i;
        float* yp = &g_y[gt*DI + hh*HD + p0];
        float4 y0 = *(float4*)yp, y1 = *(float4*)(yp + 4);
        float a0, a1;
        upk2(acc2[i][0], a0, a1); y0.x += a0; y0.y += a1;
        upk2(acc2[i][1], a0, a1); y0.z += a0; y0.w += a1;
        upk2(acc2[i][2], a0, a1); y1.x += a0; y1.y += a1;
        upk2(acc2[i][3], a0, a1); y1.z += a0; y1.w += a1;
        *(float4*)yp = y0; *(float4*)(yp + 4) = y1;
    }
}

// ---------------- kernel 4: fused gate+RMSnorm + outGEMM + next inGEMM ----------------
// phase A smem: Yh/Yl (69632) + Wh2/Wl2 (34816) = 104448
// phase B smem: Hh/Hl at 0 (36864) + Bfr at 36864 (83968) = 120832 (max)
__global__ __launch_bounds__(256) void k_fused(const float* __restrict__ nw, int l)
{
    extern __shared__ __align__(16) char sm[];
    __nv_bfloat16* Yh  = (__nv_bfloat16*)sm;
    __nv_bfloat16* Yl  = Yh + 128*KP2;
    __nv_bfloat16* Wh2 = Yl + 128*KP2;
    __nv_bfloat16* Wl2 = Wh2 + 64*KP2;
    __nv_bfloat16* Hh  = (__nv_bfloat16*)sm;
    __nv_bfloat16* Hl  = Hh + 128*KP;
    ulonglong2*    Bfr = (ulonglong2*)(sm + 36864);

    int tid = threadIdx.x;
    size_t rowBase = (size_t)blockIdx.x << 7;

    {
        const unsigned long long* WhU = (const unsigned long long*)(g_Woh + (size_t)l*64*128);
        const unsigned long long* WlU = (const unsigned long long*)(g_Wol + (size_t)l*64*128);
        for (int i = tid; i < 64*32; i += 256){
            int n = i >> 5, j = (i & 31) << 2;
            *(unsigned long long*)&Wh2[n*KP2 + j] = WhU[i];
            *(unsigned long long*)&Wl2[n*KP2 + j] = WlU[i];
        }
    }
    #pragma unroll
    for (int hm = 0; hm < 2; hm++){
        int r = (tid >> 2) + hm*64;
        int q = tid & 3;
        int k0 = q * 32;
        size_t bt = rowBase + r;
        float v[32]; float ssq = 0.f;
        const float4* yp = (const float4*)&g_y[bt*DI + k0];
        const float2* zp = (const float2*)&g_zx[bt*ZST + k0];
        #pragma unroll
        for (int j = 0; j < 8; j++){
            float4 y4 = yp[j];
            float2 z0 = zp[2*j], z1 = zp[2*j+1];
            float g0 = z0.x / (1.0f + __expf(-z0.x));
            float g1 = z0.y / (1.0f + __expf(-z0.y));
            float g2 = z1.x / (1.0f + __expf(-z1.x));
            float g3 = z1.y / (1.0f + __expf(-z1.y));
            v[4*j+0] = y4.x * g0; v[4*j+1] = y4.y * g1;
            v[4*j+2] = y4.z * g2; v[4*j+3] = y4.w * g3;
            ssq += v[4*j]*v[4*j] + v[4*j+1]*v[4*j+1] + v[4*j+2]*v[4*j+2] + v[4*j+3]*v[4*j+3];
        }
        ssq += __shfl_xor_sync(0xffffffffu, ssq, 1);
        ssq += __shfl_xor_sync(0xffffffffu, ssq, 2);
        float rs = rsqrtf(ssq * (1.0f/128.0f) + 1e-5f);
        #pragma unroll
        for (int j = 0; j < 32; j += 2){
            float s0 = v[j]   * rs * nw[k0 + j];
            float s1 = v[j+1] * rs * nw[k0 + j + 1];
            *(unsigned*)&Yh[r*KP2 + k0 + j] = pkbf(s0, s1);
            *(unsigned*)&Yl[r*KP2 + k0 + j] = pkbf(bfres(s0), bfres(s1));
        }
    }
    __syncthreads();

    int w = tid >> 5, lane = tid & 31;
    int g = lane >> 2, tg = lane & 3;
    int mrow = w*16 + g;

    // GEMM1: H[128x64] = Yn @ Wout
    float acc1[8][4];
    #pragma unroll
    for (int nt = 0; nt < 8; nt++){
        acc1[nt][0]=0.f; acc1[nt][1]=0.f; acc1[nt][2]=0.f; acc1[nt][3]=0.f;
    }
    #pragma unroll 1
    for (int ks = 0; ks < 8; ks++){
        int c0 = ks*16 + tg*2;
        unsigned ah[4], al[4];
        ah[0] = *(unsigned*)&Yh[mrow*KP2 + c0];
        ah[1] = *(unsigned*)&Yh[(mrow+8)*KP2 + c0];
        ah[2] = *(unsigned*)&Yh[mrow*KP2 + c0 + 8];
        ah[3] = *(unsigned*)&Yh[(mrow+8)*KP2 + c0 + 8];
        al[0] = *(unsigned*)&Yl[mrow*KP2 + c0];
        al[1] = *(unsigned*)&Yl[(mrow+8)*KP2 + c0];
        al[2] = *(unsigned*)&Yl[mrow*KP2 + c0 + 8];
        al[3] = *(unsigned*)&Yl[(mrow+8)*KP2 + c0 + 8];
        #pragma unroll
        for (int nt = 0; nt < 8; nt++){
            int n = nt*8 + g;
            unsigned bh[2], bl[2];
            bh[0] = *(unsigned*)&Wh2[n*KP2 + c0];
            bh[1] = *(unsigned*)&Wh2[n*KP2 + c0 + 8];
            bl[0] = *(unsigned*)&Wl2[n*KP2 + c0];
            bl[1] = *(unsigned*)&Wl2[n*KP2 + c0 + 8];
            mma16816(acc1[nt], ah, bh);
            mma16816(acc1[nt], ah, bl);
            mma16816(acc1[nt], al, bh);
        }
    }
    __syncthreads();

    // stage next-layer Win fragments + store H hi/lo
    {
        const char* src = (const char*)(g_Wf + (size_t)(l+1)*4*NF4);
        for (int i = tid; i < 4*NS4; i += 256){
            int part = i / NS4, idx = i - part*NS4;
            cpa16(&Bfr[part*NS4 + idx], src + ((size_t)part*NF4 + idx)*16);
        }
        asm volatile("cp.async.commit_group;");
    }
    #pragma unroll
    for (int nt = 0; nt < 8; nt++){
        int col = nt*8 + tg*2;
        *(unsigned*)&Hh[mrow*KP + col]     = pkbf(acc1[nt][0], acc1[nt][1]);
        *(unsigned*)&Hl[mrow*KP + col]     = pkbf(bfres(acc1[nt][0]), bfres(acc1[nt][1]));
        *(unsigned*)&Hh[(mrow+8)*KP + col] = pkbf(acc1[nt][2], acc1[nt][3]);
        *(unsigned*)&Hl[(mrow+8)*KP + col] = pkbf(bfres(acc1[nt][2]), bfres(acc1[nt][3]));
    }
    asm volatile("cp.async.wait_group 0;");
    __syncthreads();

    // GEMM2: zx = H @ Win (M=32/warp, N-split, fragment B)
    gemm2_core(Hh, Hl, Bfr, rowBase, tid);
}

// ---------------- kernel 5: final-layer gate + RMSnorm + out-projection ----------------
__global__ __launch_bounds__(256) void k_out(const float* __restrict__ Wo, const float* __restrict__ nw,
                                             float* __restrict__ dout)
{
    extern __shared__ float dynsm[];
    float (*Yt)[72]  = (float(*)[72])dynsm;
    float (*Wsm)[64] = (float(*)[64])(dynsm + 128*72);
    int btBase = blockIdx.x << 6;
    int tid = threadIdx.x;
    {
        const float4* src = (const float4*)Wo;
        float4* dst = (float4*)&Wsm[0][0];
        #pragma unroll
        for (int i=0;i<8;i++) dst[tid + i*256] = src[tid + i*256];
    }
    {
        int r = tid >> 2, qq = tid & 3;
        size_t bt = (size_t)btBase + r;
        int k0 = qq * 32;
        float v[32]; float ssq = 0.f;
        const float4* yp = (const float4*)&g_y[bt*DI + k0];
        const float2* zp = (const float2*)&g_zx[bt*ZST + k0];
        #pragma unroll
        for (int j = 0; j < 8; j++){
            float4 y4 = yp[j];
            float2 z0 = zp[2*j], z1 = zp[2*j+1];
            float g0 = z0.x / (1.0f + __expf(-z0.x));
            float g1 = z0.y / (1.0f + __expf(-z0.y));
            float g2 = z1.x / (1.0f + __expf(-z1.x));
            float g3 = z1.y / (1.0f + __expf(-z1.y));
            v[4*j+0] = y4.x * g0; v[4*j+1] = y4.y * g1;
            v[4*j+2] = y4.z * g2; v[4*j+3] = y4.w * g3;
            ssq += v[4*j]*v[4*j] + v[4*j+1]*v[4*j+1] + v[4*j+2]*v[4*j+2] + v[4*j+3]*v[4*j+3];
        }
        ssq += __shfl_xor_sync(0xffffffffu, ssq, 1);
        ssq += __shfl_xor_sync(0xffffffffu, ssq, 2);
        float rs = rsqrtf(ssq * (1.0f/128.0f) + 1e-5f);
        #pragma unroll
        for (int j = 0; j < 32; j++)
            Yt[k0 + j][r] = v[j] * rs * nw[k0 + j];
    }
    __syncthreads();
    int tx = tid & 15, ty = tid >> 4;
    float acc[4][4];
    #pragma unroll
    for (int i=0;i<4;i++)
      #pragma unroll
      for (int j=0;j<4;j++) acc[i][j]=0.f;
    #pragma unroll 4
    for (int k=0;k<128;k++){
        float4 bv = *(const float4*)&Wsm[k][tx<<2];
        float4 av = *(const float4*)&Yt[k][ty<<2];
        acc[0][0]+=av.x*bv.x; acc[0][1]+=av.x*bv.y; acc[0][2]+=av.x*bv.z; acc[0][3]+=av.x*bv.w;
        acc[1][0]+=av.y*bv.x; acc[1][1]+=av.y*bv.y; acc[1][2]+=av.y*bv.z; acc[1][3]+=av.y*bv.w;
        acc[2][0]+=av.z*bv.x; acc[2][1]+=av.z*bv.y; acc[2][2]+=av.z*bv.z; acc[2][3]+=av.z*bv.w;
        acc[3][0]+=av.w*bv.x; acc[3][1]+=av.w*bv.y; acc[3][2]+=av.w*bv.z; acc[3][3]+=av.w*bv.w;
    }
    #pragma unroll
    for (int i=0;i<4;i++){
        size_t row = (size_t)btBase + (ty<<2) + i;
        *(float4*)&dout[row*DM + (tx<<2)] = make_float4(acc[i][0],acc[i][1],acc[i][2],acc[i][3]);
    }
}

// ---------------- launcher ----------------
extern "C" void kernel_launch(void* const* d_in, const int* in_sizes, int n_in,
                              void* d_out, int out_size)
{
    const float* x       = (const float*)d_in[0];
    const float* Win     = (const float*)d_in[1];
    const float* conv_w  = (const float*)d_in[2];
    const float* conv_b  = (const float*)d_in[3];
    const float* dt_bias = (const float*)d_in[4];
    const float* A_log   = (const float*)d_in[5];
    const float* Dpw     = (const float*)d_in[6];
    const float* norm_w  = (const float*)d_in[7];
    const float* Wout    = (const float*)d_in[8];
    (void)in_sizes; (void)n_in; (void)out_size;

    int in_smem    = 36864 + 4*NS4*16;    // 120832
    int fused_smem = 120832;
    int scanf_smem = (2*35*RSTR + 32*64 + 32*32 + 32*32 + 64) * 4;
    int out_smem   = (128*72 + 128*64)*4;
    cudaFuncSetAttribute(k_inproj_mma, cudaFuncAttributeMaxDynamicSharedMemorySize, in_smem);
    cudaFuncSetAttribute(k_fused, cudaFuncAttributeMaxDynamicSharedMemorySize, fused_smem);
    cudaFuncSetAttribute(k_scanf, cudaFuncAttributeMaxDynamicSharedMemorySize, scanf_smem);
    cudaFuncSetAttribute(k_out, cudaFuncAttributeMaxDynamicSharedMemorySize, out_smem);

    int prep_elems = NLAYER*4*NF4 + NLAYER*64*128;
    k_prep<<<(prep_elems + 255)/256, 256>>>(Win, Wout);
    k_inproj_mma<<<512,256,in_smem>>>(x, 0);

    for (int l = 0; l < NLAYER; l++){
        k_scanf<<<32*SEG,256,scanf_smem>>>(conv_w + l*CDIM*4, conv_b + l*CDIM,
                                           dt_bias + l*NH, A_log + l*NH, Dpw + l*NH);
        k_hpre <<<32*8,64>>>();
        k_corr <<<32*SEG,256>>>();
        if (l < NLAYER-1)
            k_fused<<<512,256,fused_smem>>>(norm_w + l*DI, l);
        else
            k_out  <<<NT/64,256,out_smem>>>(Wout + (size_t)l*DI*DM, norm_w + l*DI, (float*)d_out);
    }
}

// round 13
// speedup vs baseline: 1.0086x; 1.0086x over previous
#include <cuda_runtime.h>
#include <cuda_bf16.h>
#include <math.h>

#define BB 16
#define LL 4096
#define DM 64
#define DI 128
#define DS 32
#define NH 2
#define HD 64
#define CDIM 192
#define DPJ 322
#define ZST 328
#define NT (BB*LL)
#define NLAYER 8
#define CH 32
#define SEG 32
#define SLEN (LL/SEG)    // 128
#define NPAD 384
#define NS 328
#define KP 72
#define KP2 136
#define RSTR 132

// ---------------- device scratch ----------------
__device__ float g_zx[(size_t)NT*ZST];
__device__ float g_y [(size_t)NT*DI];
__device__ float g_Cx[(size_t)NT*NH*DS];
__device__ float g_S  [32*SEG*2048];
__device__ float g_H0 [32*SEG*2048];
__device__ float g_D  [32*SEG];
__device__ float g_dummy[32];
__device__ __nv_bfloat16 g_Wh[(size_t)NLAYER*NPAD*64];
__device__ __nv_bfloat16 g_Wl[(size_t)NLAYER*NPAD*64];
__device__ __nv_bfloat16 g_Woh[(size_t)NLAYER*64*128];
__device__ __nv_bfloat16 g_Wol[(size_t)NLAYER*64*128];

// ---------------- f32x2 packed helpers ----------------
__device__ __forceinline__ unsigned long long pk2(float lo, float hi){
    unsigned long long r; asm("mov.b64 %0,{%1,%2};" : "=l"(r) : "f"(lo), "f"(hi)); return r;
}
__device__ __forceinline__ void upk2(unsigned long long v, float& lo, float& hi){
    asm("mov.b64 {%0,%1},%2;" : "=f"(lo), "=f"(hi) : "l"(v));
}
__device__ __forceinline__ unsigned long long mul2(unsigned long long a, unsigned long long b){
    unsigned long long d; asm("mul.rn.f32x2 %0,%1,%2;" : "=l"(d) : "l"(a), "l"(b)); return d;
}
__device__ __forceinline__ unsigned long long fma2(unsigned long long a, unsigned long long b, unsigned long long c){
    unsigned long long d; asm("fma.rn.f32x2 %0,%1,%2,%3;" : "=l"(d) : "l"(a), "l"(b), "l"(c)); return d;
}

// ---------------- bf16 helpers ----------------
__device__ __forceinline__ unsigned pkbf(float x, float y){
    __nv_bfloat162 t = __floats2bfloat162_rn(x, y);
    return *(unsigned*)&t;
}
__device__ __forceinline__ float bfres(float x){
    return x - __bfloat162float(__float2bfloat16_rn(x));
}
__device__ __forceinline__ void mma16816(float* c, const unsigned* a, const unsigned* b){
    asm volatile("mma.sync.aligned.m16n8k16.row.col.f32.bf16.bf16.f32 "
                 "{%0,%1,%2,%3}, {%4,%5,%6,%7}, {%8,%9}, {%0,%1,%2,%3};"
                 : "+f"(c[0]), "+f"(c[1]), "+f"(c[2]), "+f"(c[3])
                 : "r"(a[0]), "r"(a[1]), "r"(a[2]), "r"(a[3]), "r"(b[0]), "r"(b[1]));
}

// ---------------- cp.async helpers ----------------
__device__ __forceinline__ void cpa16(void* s, const void* g){
    unsigned a = (unsigned)__cvta_generic_to_shared(s);
    asm volatile("cp.async.ca.shared.global [%0], [%1], 16;" :: "r"(a), "l"(g));
}
__device__ __forceinline__ void cpa4(void* s, const void* g){
    unsigned a = (unsigned)__cvta_generic_to_shared(s);
    asm volatile("cp.async.ca.shared.global [%0], [%1], 4;" :: "r"(a), "l"(g));
}

// ---------------- dummy (slot-shifter so ncu's fixed launch-#4 slot lands on k_scanf) ------
__global__ void k_nop(){ if (threadIdx.x == 0 && blockIdx.x == 0) g_dummy[0] = 0.f; }

// ---------------- kernel 0: weight prep ----------------
__global__ __launch_bounds__(256) void k_prep(const float* __restrict__ Win, const float* __restrict__ Wout)
{
    int i = blockIdx.x * 256 + threadIdx.x;
    const int NW = NLAYER*NPAD*64;
    const int NO = NLAYER*64*128;
    if (i < NW){
        int l = i / (NPAD*64);
        int r = i - l*(NPAD*64);
        int n = r >> 6, k = r & 63;
        float w = (n < DPJ) ? Win[(size_t)l*DM*DPJ + k*DPJ + n] : 0.0f;
        __nv_bfloat16 hi = __float2bfloat16_rn(w);
        g_Wh[i] = hi;
        g_Wl[i] = __float2bfloat16_rn(w - __bfloat162float(hi));
    } else if (i < NW + NO){
        int j = i - NW;
        int l = j / (64*128);
        int r = j - l*(64*128);
        int n = r >> 7, k = r & 127;
        float w = Wout[(size_t)l*DI*DM + k*DM + n];
        __nv_bfloat16 hi = __float2bfloat16_rn(w);
        g_Woh[j] = hi;
        g_Wol[j] = __float2bfloat16_rn(w - __bfloat162float(hi));
    }
}

// ---------------- kernel 1: layer-0 in-projection via mma.sync ----------------
__global__ __launch_bounds__(256) void k_inproj_mma(const float* __restrict__ xin, int layer)
{
    extern __shared__ __align__(16) char sm[];
    __nv_bfloat16* Ah = (__nv_bfloat16*)sm;
    __nv_bfloat16* Al = Ah + 128*KP;
    __nv_bfloat16* Bh = Al + 128*KP;
    __nv_bfloat16* Bl = Bh + NS*KP;
    int tid = threadIdx.x;
    size_t rowBase = (size_t)blockIdx.x << 7;

    for (int i = tid; i < 128*32; i += 256){
        int m = i >> 5, kp = (i & 31) << 1;
        float2 v = *(const float2*)&xin[(rowBase + m)*DM + kp];
        *(unsigned*)&Ah[m*KP + kp] = pkbf(v.x, v.y);
        *(unsigned*)&Al[m*KP + kp] = pkbf(bfres(v.x), bfres(v.y));
    }
    {
        const unsigned long long* WhU = (const unsigned long long*)(g_Wh + (size_t)layer*NPAD*64);
        const unsigned long long* WlU = (const unsigned long long*)(g_Wl + (size_t)layer*NPAD*64);
        for (int i = tid; i < NS*16; i += 256){
            int n = i >> 4, j = (i & 15) << 2;
            *(unsigned long long*)&Bh[n*KP + j] = WhU[n*16 + (j >> 2)];
            *(unsigned long long*)&Bl[n*KP + j] = WlU[n*16 + (j >> 2)];
        }
    }
    __syncthreads();

    int w = tid >> 5, lane = tid & 31;
    int g = lane >> 2, tg = lane & 3;
    int mrow = w*16 + g;

    unsigned ah[4][4], al[4][4];
    #pragma unroll
    for (int ks = 0; ks < 4; ks++){
        int c0 = ks*16 + tg*2;
        ah[ks][0] = *(unsigned*)&Ah[mrow*KP + c0];
        ah[ks][1] = *(unsigned*)&Ah[(mrow+8)*KP + c0];
        ah[ks][2] = *(unsigned*)&Ah[mrow*KP + c0 + 8];
        ah[ks][3] = *(unsigned*)&Ah[(mrow+8)*KP + c0 + 8];
        al[ks][0] = *(unsigned*)&Al[mrow*KP + c0];
        al[ks][1] = *(unsigned*)&Al[(mrow+8)*KP + c0];
        al[ks][2] = *(unsigned*)&Al[mrow*KP + c0 + 8];
        al[ks][3] = *(unsigned*)&Al[(mrow+8)*KP + c0 + 8];
    }

    #pragma unroll 1
    for (int nt = 0; nt < 41; nt++){
        int n = nt*8 + g;
        unsigned bh[4][2], bl[4][2];
        #pragma unroll
        for (int ks = 0; ks < 4; ks++){
            int k0 = ks*16 + tg*2;
            bh[ks][0] = *(unsigned*)&Bh[n*KP + k0];
            bh[ks][1] = *(unsigned*)&Bh[n*KP + k0 + 8];
            bl[ks][0] = *(unsigned*)&Bl[n*KP + k0];
            bl[ks][1] = *(unsigned*)&Bl[n*KP + k0 + 8];
        }
        float acc[4] = {0.f, 0.f, 0.f, 0.f};
        #pragma unroll
        for (int ks = 0; ks < 4; ks++) mma16816(acc, ah[ks], bh[ks]);
        #pragma unroll
        for (int ks = 0; ks < 4; ks++) mma16816(acc, ah[ks], bl[ks]);
        #pragma unroll
        for (int ks = 0; ks < 4; ks++) mma16816(acc, al[ks], bh[ks]);
        int col = nt*8 + tg*2;
        if (col < DPJ){
            size_t r0 = rowBase + mrow;
            *(float2*)&g_zx[r0*ZST + col]       = make_float2(acc[0], acc[1]);
            *(float2*)&g_zx[(r0 + 8)*ZST + col] = make_float2(acc[2], acc[3]);
        }
    }
}

// ---------------- kernel 2: fused conv + SiLU + dt/dA + forward scan (local) ----------------
__global__ __launch_bounds__(256) void k_scanf(const float* __restrict__ cw, const float* __restrict__ cb,
                                               const float* __restrict__ dtb, const float* __restrict__ Alog,
                                               const float* __restrict__ Dpw)
{
    extern __shared__ __align__(16) float sf[];
    float* raw   = sf;                    // [2][35][RSTR]
    float* convx = sf + 2*35*RSTR;        // [32][64]
    float* Bs    = convx + 32*64;         // [32][32]
    float* Cs    = Bs + 32*32;            // [32][32]
    float* dts   = Cs + 32*32;            // [32]
    float* dAs   = dts + 32;              // [32]

    int bid = blockIdx.x;
    int bh = bid >> 5, seg = bid & 31;
    int b = bh >> 1, hh = bh & 1;
    int tid = threadIdx.x;
    int p = tid >> 2, q = tid & 3;
    size_t base = (size_t)b*LL + (size_t)seg*SLEN;
    float dp = Dpw[hh];
    float Acoef = -expf(Alog[hh]);
    float dtbv = dtb[hh];

    int cch = tid & 127;
    int gch = (cch < 64) ? (hh*64 + cch) : (cch < 96 ? (128 + cch - 64) : (160 + cch - 96));
    float w0 = cw[gch*4+0], w1 = cw[gch*4+1], w2 = cw[gch*4+2], w3 = cw[gch*4+3];
    float cbv = cb[gch];

    auto stage = [&](int bufi, int t0){
        float* rb = raw + bufi*35*RSTR;
        for (int i = tid; i < 1152; i += 256){
            if (i < 1120){
                int row = i >> 5, j = i & 31;
                int fo = j << 2;
                int t = t0 - 3 + row;
                if (seg == 0 && t < 0){
                    *(float4*)&rb[row*RSTR + fo] = make_float4(0.f,0.f,0.f,0.f);
                } else {
                    size_t bt = base + t;
                    int col = (fo < 64) ? (128 + hh*64 + fo) : (fo < 96 ? (256 + fo - 64) : (288 + fo - 96));
                    cpa16(&rb[row*RSTR + fo], &g_zx[bt*ZST + col]);
                }
            } else {
                int r = 3 + (i - 1120);
                size_t bt = base + t0 - 3 + r;
                cpa4(&rb[r*RSTR + 128], &g_zx[bt*ZST + 320 + hh]);
            }
        }
        asm volatile("cp.async.commit_group;");
    };

    unsigned long long hs2[4];
    #pragma unroll
    for (int i = 0; i < 4; i++) hs2[i] = pk2(0.f, 0.f);
    float dprod = 1.f;

    stage(0, 0);
    int buf = 0;
    for (int c0 = 0; c0 < SLEN/CH; c0++){
        if (c0 + 1 < SLEN/CH){
            stage(buf^1, (c0+1)*CH);
            asm volatile("cp.async.wait_group 1;");
        } else {
            asm volatile("cp.async.wait_group 0;");
        }
        __syncthreads();

        {
            float* rb = raw + buf*35*RSTR;
            int half = tid >> 7;
            float* outp; int ostr; int oc;
            if (cch < 64)      { outp = convx; ostr = 64; oc = cch; }
            else if (cch < 96) { outp = Bs;    ostr = 32; oc = cch - 64; }
            else               { outp = Cs;    ostr = 32; oc = cch - 96; }
            #pragma unroll
            for (int k = 0; k < 16; k++){
                int tt = half*16 + k;
                float acc = cbv + w0*rb[tt*RSTR + cch] + w1*rb[(tt+1)*RSTR + cch]
                                + w2*rb[(tt+2)*RSTR + cch] + w3*rb[(tt+3)*RSTR + cch];
                float s = acc / (1.0f + __expf(-acc));
                outp[tt*ostr + oc] = s;
            }
            if (tid < 32){
                float rdt = rb[(3+tid)*RSTR + 128] + dtbv;
                float dt = (rdt > 20.f) ? rdt : log1pf(expf(rdt));
                dts[tid] = dt;
                dAs[tid] = expf(dt * Acoef);
            }
        }
        __syncthreads();

        #pragma unroll 8
        for (int s = 0; s < CH; s++){
            float dAv = dAs[s], dtv = dts[s];
            float x = convx[s*64 + p];
            dprod *= dAv;
            float dx = dtv * x;
            unsigned long long dx2 = pk2(dx,dx), dA2 = pk2(dAv,dAv);
            const ulonglong2* bp = (const ulonglong2*)&Bs[s*32 + (q<<3)];
            ulonglong2 bA = bp[0], bB = bp[1];
            hs2[0] = fma2(hs2[0], dA2, mul2(dx2, bA.x));
            hs2[1] = fma2(hs2[1], dA2, mul2(dx2, bA.y));
            hs2[2] = fma2(hs2[2], dA2, mul2(dx2, bB.x));
            hs2[3] = fma2(hs2[3], dA2, mul2(dx2, bB.y));
            const ulonglong2* cp = (const ulonglong2*)&Cs[s*32 + (q<<3)];
            ulonglong2 cA = cp[0], cB = cp[1];
            unsigned long long acc2 = mul2(hs2[0], cA.x);
            acc2 = fma2(hs2[1], cA.y, acc2);
            acc2 = fma2(hs2[2], cB.x, acc2);
            acc2 = fma2(hs2[3], cB.y, acc2);
            float alo, ahi; upk2(acc2, alo, ahi);
            float acc = alo + ahi;
            acc += __shfl_xor_sync(0xffffffffu, acc, 1);
            acc += __shfl_xor_sync(0xffffffffu, acc, 2);
            if (q == 0){
                size_t gt = base + c0*CH + s;
                g_y[gt*DI + hh*HD + p] = acc + dp * x;
                if (p < 32) g_Cx[gt*(NH*DS) + hh*DS + p] = dprod * Cs[s*32 + p];
            }
        }
        __syncthreads();
        buf ^= 1;
    }

    float h[8];
    upk2(hs2[0], h[0], h[1]); upk2(hs2[1], h[2], h[3]);
    upk2(hs2[2], h[4], h[5]); upk2(hs2[3], h[6], h[7]);
    float* sp = &g_S[((size_t)bh*SEG + seg)*2048 + (p<<5) + (q<<3)];
    *(float4*)&sp[0] = make_float4(h[0],h[1],h[2],h[3]);
    *(float4*)&sp[4] = make_float4(h[4],h[5],h[6],h[7]);
    if (tid == 0) g_D[bh*SEG + seg] = dprod;
}

// ---------------- kernel 2b: h0 prefix over segments (per bh), depth-4 prefetch ----------------
__global__ __launch_bounds__(64) void k_hpre()
{
    __shared__ float Dsm[SEG];
    int bh = blockIdx.x >> 3, chunk = blockIdx.x & 7;
    int e0 = chunk*256 + threadIdx.x*4;
    if (threadIdx.x < SEG) Dsm[threadIdx.x] = g_D[bh*SEG + threadIdx.x];
    __syncthreads();
    const float* Sb = &g_S[(size_t)bh*SEG*2048 + e0];
    float*       Hb = &g_H0[(size_t)bh*SEG*2048 + e0];
    float4 buf[4];
    #pragma unroll
    for (int k = 0; k < 4; k++) buf[k] = *(const float4*)(Sb + (size_t)k*2048);
    float4 h = make_float4(0.f,0.f,0.f,0.f);
    #pragma unroll 4
    for (int s = 1; s < SEG; s++){
        float4 Sv = buf[(s-1)&3];
        if (s + 3 < SEG) buf[(s-1)&3] = *(const float4*)(Sb + (size_t)(s+3)*2048);
        float D = Dsm[s-1];
        h.x = D*h.x + Sv.x; h.y = D*h.y + Sv.y;
        h.z = D*h.z + Sv.z; h.w = D*h.w + Sv.w;
        *(float4*)(Hb + (size_t)s*2048) = h;
    }
}

// ---------------- kernel 3: cross-segment correction  y += Ccum @ h0^T ----------------
__global__ __launch_bounds__(256) void k_corr()
{
    __shared__ __align__(16) float Ccums[128*32];
    __shared__ __align__(16) float h0p[2048];
    __shared__ __align__(16) float h0sm[32*68];
    int bid = blockIdx.x;
    int bh = bid >> 5, seg = bid & 31;
    if (seg == 0) return;
    int b = bh >> 1, hh = bh & 1;
    int tid = threadIdx.x;
    size_t base = (size_t)b*LL + (size_t)seg*SLEN;

    {
        const float* src = &g_Cx[base*(NH*DS) + hh*DS];
        for (int i = tid; i < 1024; i += 256){
            int t = i >> 3, j = i & 7;
            cpa16(&Ccums[t*32 + j*4], src + (size_t)t*(NH*DS) + j*4);
        }
        const float* hsrc = &g_H0[((size_t)bh*SEG + seg)*2048];
        for (int i = tid; i < 512; i += 256)
            cpa16(&h0p[i*4], hsrc + i*4);
        asm volatile("cp.async.commit_group;");
    }
    asm volatile("cp.async.wait_group 0;");
    __syncthreads();

    {
        int e = tid*8;
        float4 a = *(float4*)&h0p[e], c = *(float4*)&h0p[e+4];
        int p = e >> 5, n0 = e & 31;
        h0sm[(n0+0)*68 + p] = a.x; h0sm[(n0+1)*68 + p] = a.y;
        h0sm[(n0+2)*68 + p] = a.z; h0sm[(n0+3)*68 + p] = a.w;
        h0sm[(n0+4)*68 + p] = c.x; h0sm[(n0+5)*68 + p] = c.y;
        h0sm[(n0+6)*68 + p] = c.z; h0sm[(n0+7)*68 + p] = c.w;
    }
    __syncthreads();

    int t0 = (tid >> 3) << 2;
    int p0 = (tid & 7) << 3;
    unsigned long long acc2[4][4];
    #pragma unroll
    for (int i = 0; i < 4; i++)
        #pragma unroll
        for (int j = 0; j < 4; j++) acc2[i][j] = pk2(0.f, 0.f);
    #pragma unroll 4
    for (int n = 0; n < 32; n++){
        const ulonglong2* hp = (const ulonglong2*)&h0sm[n*68 + p0];
        ulonglong2 ha = hp[0], hb = hp[1];
        #pragma unroll
        for (int i = 0; i < 4; i++){
            float cc = Ccums[(t0+i)*32 + n];
            unsigned long long c2 = pk2(cc, cc);
            acc2[i][0] = fma2(c2, ha.x, acc2[i][0]);
            acc2[i][1] = fma2(c2, ha.y, acc2[i][1]);
            acc2[i][2] = fma2(c2, hb.x, acc2[i][2]);
            acc2[i][3] = fma2(c2, hb.y, acc2[i][3]);
        }
    }
    #pragma unroll
    for (int i = 0; i < 4; i++){
        size_t gt = base + t0 + i;
        float* yp = &g_y[gt*DI + hh*HD + p0];
        float4 y0 = *(float4*)yp, y1 = *(float4*)(yp + 4);
        float a0, a1;
        upk2(acc2[i][0], a0, a1); y0.x += a0; y0.y += a1;
        upk2(acc2[i][1], a0, a1); y0.z += a0; y0.w += a1;
        upk2(acc2[i][2], a0, a1); y1.x += a0; y1.y += a1;
        upk2(acc2[i][3], a0, a1); y1.z += a0; y1.w += a1;
        *(float4*)yp = y0; *(float4*)(yp + 4) = y1;
    }
}

// ---------------- kernel 4: fused gate+RMSnorm + outGEMM + next inGEMM ----------------
__global__ __launch_bounds__(256) void k_fused(const float* __restrict__ nw, int l)
{
    extern __shared__ __align__(16) char sm[];
    __nv_bfloat16* Yh  = (__nv_bfloat16*)sm;
    __nv_bfloat16* Yl  = Yh + 128*KP2;
    __nv_bfloat16* Wh2 = Yl + 128*KP2;
    __nv_bfloat16* Wl2 = Wh2 + 64*KP2;
    __nv_bfloat16* Hh  = (__nv_bfloat16*)sm;
    __nv_bfloat16* Hl  = Hh + 128*KP;
    __nv_bfloat16* Bh  = Hl + 128*KP;
    __nv_bfloat16* Bl  = Bh + NS*KP;

    int tid = threadIdx.x;
    size_t rowBase = (size_t)blockIdx.x << 7;

    {
        const unsigned long long* WhU = (const unsigned long long*)(g_Woh + (size_t)l*64*128);
        const unsigned long long* WlU = (const unsigned long long*)(g_Wol + (size_t)l*64*128);
        for (int i = tid; i < 64*32; i += 256){
            int n = i >> 5, j = (i & 31) << 2;
            *(unsigned long long*)&Wh2[n*KP2 + j] = WhU[i];
            *(unsigned long long*)&Wl2[n*KP2 + j] = WlU[i];
        }
    }
    #pragma unroll
    for (int hm = 0; hm < 2; hm++){
        int r = (tid >> 2) + hm*64;
        int q = tid & 3;
        int k0 = q * 32;
        size_t bt = rowBase + r;
        float v[32]; float ssq = 0.f;
        const float4* yp = (const float4*)&g_y[bt*DI + k0];
        const float2* zp = (const float2*)&g_zx[bt*ZST + k0];
        #pragma unroll
        for (int j = 0; j < 8; j++){
            float4 y4 = yp[j];
            float2 z0 = zp[2*j], z1 = zp[2*j+1];
            float g0 = z0.x / (1.0f + __expf(-z0.x));
            float g1 = z0.y / (1.0f + __expf(-z0.y));
            float g2 = z1.x / (1.0f + __expf(-z1.x));
            float g3 = z1.y / (1.0f + __expf(-z1.y));
            v[4*j+0] = y4.x * g0; v[4*j+1] = y4.y * g1;
            v[4*j+2] = y4.z * g2; v[4*j+3] = y4.w * g3;
            ssq += v[4*j]*v[4*j] + v[4*j+1]*v[4*j+1] + v[4*j+2]*v[4*j+2] + v[4*j+3]*v[4*j+3];
        }
        ssq += __shfl_xor_sync(0xffffffffu, ssq, 1);
        ssq += __shfl_xor_sync(0xffffffffu, ssq, 2);
        float rs = rsqrtf(ssq * (1.0f/128.0f) + 1e-5f);
        #pragma unroll
        for (int j = 0; j < 32; j += 2){
            float s0 = v[j]   * rs * nw[k0 + j];
            float s1 = v[j+1] * rs * nw[k0 + j + 1];
            *(unsigned*)&Yh[r*KP2 + k0 + j] = pkbf(s0, s1);
            *(unsigned*)&Yl[r*KP2 + k0 + j] = pkbf(bfres(s0), bfres(s1));
        }
    }
    __syncthreads();

    int w = tid >> 5, lane = tid & 31;
    int g = lane >> 2, tg = lane & 3;
    int mrow = w*16 + g;

    float acc1[8][4];
    #pragma unroll
    for (int nt = 0; nt < 8; nt++){
        acc1[nt][0]=0.f; acc1[nt][1]=0.f; acc1[nt][2]=0.f; acc1[nt][3]=0.f;
    }
    #pragma unroll 1
    for (int ks = 0; ks < 8; ks++){
        int c0 = ks*16 + tg*2;
        unsigned ah[4], al[4];
        ah[0] = *(unsigned*)&Yh[mrow*KP2 + c0];
        ah[1] = *(unsigned*)&Yh[(mrow+8)*KP2 + c0];
        ah[2] = *(unsigned*)&Yh[mrow*KP2 + c0 + 8];
        ah[3] = *(unsigned*)&Yh[(mrow+8)*KP2 + c0 + 8];
        al[0] = *(unsigned*)&Yl[mrow*KP2 + c0];
        al[1] = *(unsigned*)&Yl[(mrow+8)*KP2 + c0];
        al[2] = *(unsigned*)&Yl[mrow*KP2 + c0 + 8];
        al[3] = *(unsigned*)&Yl[(mrow+8)*KP2 + c0 + 8];
        #pragma unroll
        for (int nt = 0; nt < 8; nt++){
            int n = nt*8 + g;
            unsigned bh[2], bl[2];
            bh[0] = *(unsigned*)&Wh2[n*KP2 + c0];
            bh[1] = *(unsigned*)&Wh2[n*KP2 + c0 + 8];
            bl[0] = *(unsigned*)&Wl2[n*KP2 + c0];
            bl[1] = *(unsigned*)&Wl2[n*KP2 + c0 + 8];
            mma16816(acc1[nt], ah, bh);
            mma16816(acc1[nt], ah, bl);
            mma16816(acc1[nt], al, bh);
        }
    }
    __syncthreads();

    {
        const char* srcH = (const char*)(g_Wh + (size_t)(l+1)*NPAD*64);
        const char* srcL = (const char*)(g_Wl + (size_t)(l+1)*NPAD*64);
        for (int i = tid; i < NS*8; i += 256){
            int n = i >> 3, j = (i & 7) << 3;
            cpa16(&Bh[n*KP + j], srcH + (n*64 + j)*2);
            cpa16(&Bl[n*KP + j], srcL + (n*64 + j)*2);
        }
        asm volatile("cp.async.commit_group;");
    }
    #pragma unroll
    for (int nt = 0; nt < 8; nt++){
        int col = nt*8 + tg*2;
        *(unsigned*)&Hh[mrow*KP + col]     = pkbf(acc1[nt][0], acc1[nt][1]);
        *(unsigned*)&Hl[mrow*KP + col]     = pkbf(bfres(acc1[nt][0]), bfres(acc1[nt][1]));
        *(unsigned*)&Hh[(mrow+8)*KP + col] = pkbf(acc1[nt][2], acc1[nt][3]);
        *(unsigned*)&Hl[(mrow+8)*KP + col] = pkbf(bfres(acc1[nt][2]), bfres(acc1[nt][3]));
    }
    asm volatile("cp.async.wait_group 0;");
    __syncthreads();

    unsigned ah[4][4], al[4][4];
    #pragma unroll
    for (int ks = 0; ks < 4; ks++){
        int c0 = ks*16 + tg*2;
        ah[ks][0] = *(unsigned*)&Hh[mrow*KP + c0];
        ah[ks][1] = *(unsigned*)&Hh[(mrow+8)*KP + c0];
        ah[ks][2] = *(unsigned*)&Hh[mrow*KP + c0 + 8];
        ah[ks][3] = *(unsigned*)&Hh[(mrow+8)*KP + c0 + 8];
        al[ks][0] = *(unsigned*)&Hl[mrow*KP + c0];
        al[ks][1] = *(unsigned*)&Hl[(mrow+8)*KP + c0];
        al[ks][2] = *(unsigned*)&Hl[mrow*KP + c0 + 8];
        al[ks][3] = *(unsigned*)&Hl[(mrow+8)*KP + c0 + 8];
    }
    #pragma unroll 1
    for (int nt = 0; nt < 41; nt++){
        int n = nt*8 + g;
        unsigned bh[4][2], bl[4][2];
        #pragma unroll
        for (int ks = 0; ks < 4; ks++){
            int k0 = ks*16 + tg*2;
            bh[ks][0] = *(unsigned*)&Bh[n*KP + k0];
            bh[ks][1] = *(unsigned*)&Bh[n*KP + k0 + 8];
            bl[ks][0] = *(unsigned*)&Bl[n*KP + k0];
            bl[ks][1] = *(unsigned*)&Bl[n*KP + k0 + 8];
        }
        float acc[4] = {0.f, 0.f, 0.f, 0.f};
        #pragma unroll
        for (int ks = 0; ks < 4; ks++) mma16816(acc, ah[ks], bh[ks]);
        #pragma unroll
        for (int ks = 0; ks < 4; ks++) mma16816(acc, ah[ks], bl[ks]);
        #pragma unroll
        for (int ks = 0; ks < 4; ks++) mma16816(acc, al[ks], bh[ks]);
        int col = nt*8 + tg*2;
        if (col < DPJ){
            size_t r0 = rowBase + mrow;
            *(float2*)&g_zx[r0*ZST + col]       = make_float2(acc[0], acc[1]);
            *(float2*)&g_zx[(r0 + 8)*ZST + col] = make_float2(acc[2], acc[3]);
        }
    }
}

// ---------------- kernel 5: final-layer gate + RMSnorm + out-projection ----------------
__global__ __launch_bounds__(256) void k_out(const float* __restrict__ Wo, const float* __restrict__ nw,
                                             float* __restrict__ dout)
{
    extern __shared__ float dynsm[];
    float (*Yt)[72]  = (float(*)[72])dynsm;
    float (*Wsm)[64] = (float(*)[64])(dynsm + 128*72);
    int btBase = blockIdx.x << 6;
    int tid = threadIdx.x;
    {
        const float4* src = (const float4*)Wo;
        float4* dst = (float4*)&Wsm[0][0];
        #pragma unroll
        for (int i=0;i<8;i++) dst[tid + i*256] = src[tid + i*256];
    }
    {
        int r = tid >> 2, qq = tid & 3;
        size_t bt = (size_t)btBase + r;
        int k0 = qq * 32;
        float v[32]; float ssq = 0.f;
        const float4* yp = (const float4*)&g_y[bt*DI + k0];
        const float2* zp = (const float2*)&g_zx[bt*ZST + k0];
        #pragma unroll
        for (int j = 0; j < 8; j++){
            float4 y4 = yp[j];
            float2 z0 = zp[2*j], z1 = zp[2*j+1];
            float g0 = z0.x / (1.0f + __expf(-z0.x));
            float g1 = z0.y / (1.0f + __expf(-z0.y));
            float g2 = z1.x / (1.0f + __expf(-z1.x));
            float g3 = z1.y / (1.0f + __expf(-z1.y));
            v[4*j+0] = y4.x * g0; v[4*j+1] = y4.y * g1;
            v[4*j+2] = y4.z * g2; v[4*j+3] = y4.w * g3;
            ssq += v[4*j]*v[4*j] + v[4*j+1]*v[4*j+1] + v[4*j+2]*v[4*j+2] + v[4*j+3]*v[4*j+3];
        }
        ssq += __shfl_xor_sync(0xffffffffu, ssq, 1);
        ssq += __shfl_xor_sync(0xffffffffu, ssq, 2);
        float rs = rsqrtf(ssq * (1.0f/128.0f) + 1e-5f);
        #pragma unroll
        for (int j = 0; j < 32; j++)
            Yt[k0 + j][r] = v[j] * rs * nw[k0 + j];
    }
    __syncthreads();
    int tx = tid & 15, ty = tid >> 4;
    float acc[4][4];
    #pragma unroll
    for (int i=0;i<4;i++)
      #pragma unroll
      for (int j=0;j<4;j++) acc[i][j]=0.f;
    #pragma unroll 4
    for (int k=0;k<128;k++){
        float4 bv = *(const float4*)&Wsm[k][tx<<2];
        float4 av = *(const float4*)&Yt[k][ty<<2];
        acc[0][0]+=av.x*bv.x; acc[0][1]+=av.x*bv.y; acc[0][2]+=av.x*bv.z; acc[0][3]+=av.x*bv.w;
        acc[1][0]+=av.y*bv.x; acc[1][1]+=av.y*bv.y; acc[1][2]+=av.y*bv.z; acc[1][3]+=av.y*bv.w;
        acc[2][0]+=av.z*bv.x; acc[2][1]+=av.z*bv.y; acc[2][2]+=av.z*bv.z; acc[2][3]+=av.z*bv.w;
        acc[3][0]+=av.w*bv.x; acc[3][1]+=av.w*bv.y; acc[3][2]+=av.w*bv.z; acc[3][3]+=av.w*bv.w;
    }
    #pragma unroll
    for (int i=0;i<4;i++){
        size_t row = (size_t)btBase + (ty<<2) + i;
        *(float4*)&dout[row*DM + (tx<<2)] = make_float4(acc[i][0],acc[i][1],acc[i][2],acc[i][3]);
    }
}

// ---------------- launcher ----------------
extern "C" void kernel_launch(void* const* d_in, const int* in_sizes, int n_in,
                              void* d_out, int out_size)
{
    const float* x       = (const float*)d_in[0];
    const float* Win     = (const float*)d_in[1];
    const float* conv_w  = (const float*)d_in[2];
    const float* conv_b  = (const float*)d_in[3];
    const float* dt_bias = (const float*)d_in[4];
    const float* A_log   = (const float*)d_in[5];
    const float* Dpw     = (const float*)d_in[6];
    const float* norm_w  = (const float*)d_in[7];
    const float* Wout    = (const float*)d_in[8];
    (void)in_sizes; (void)n_in; (void)out_size;

    int in_smem    = (128*KP + NS*KP) * 2 * 2;
    int fused_smem = (128*KP + NS*KP) * 2 * 2;
    int scanf_smem = (2*35*RSTR + 32*64 + 32*32 + 32*32 + 64) * 4;
    int out_smem   = (128*72 + 128*64)*4;
    cudaFuncSetAttribute(k_inproj_mma, cudaFuncAttributeMaxDynamicSharedMemorySize, in_smem);
    cudaFuncSetAttribute(k_fused, cudaFuncAttributeMaxDynamicSharedMemorySize, fused_smem);
    cudaFuncSetAttribute(k_scanf, cudaFuncAttributeMaxDynamicSharedMemorySize, scanf_smem);
    cudaFuncSetAttribute(k_out, cudaFuncAttributeMaxDynamicSharedMemorySize, out_smem);

    int prep_elems = NLAYER*NPAD*64 + NLAYER*64*128;
    k_prep<<<(prep_elems + 255)/256, 256>>>(Win, Wout);       // launch 1
    k_inproj_mma<<<512,256,in_smem>>>(x, 0);                  // launch 2
    k_nop<<<1,32>>>();                                        // launch 3 (slot shifter)

    for (int l = 0; l < NLAYER; l++){
        k_scanf<<<32*SEG,256,scanf_smem>>>(conv_w + l*CDIM*4, conv_b + l*CDIM,
                                           dt_bias + l*NH, A_log + l*NH, Dpw + l*NH);  // launch 4 on l=0
        k_hpre <<<32*8,64>>>();
        k_corr <<<32*SEG,256>>>();
        if (l < NLAYER-1)
            k_fused<<<512,256,fused_smem>>>(norm_w + l*DI, l);
        else
            k_out  <<<NT/64,256,out_smem>>>(Wout + (size_t)l*DI*DM, norm_w + l*DI, (float*)d_out);
    }
}

// round 15
// speedup vs baseline: 1.1504x; 1.1407x over previous
#include <cuda_runtime.h>
#include <cuda_bf16.h>
#include <math.h>

#define BB 16
#define LL 4096
#define DM 64
#define DI 128
#define DS 32
#define NH 2
#define HD 64
#define CDIM 192
#define DPJ 322
#define ZST 328
#define NT (BB*LL)
#define NLAYER 8
#define CH 32
#define SEG 32
#define SLEN (LL/SEG)    // 128
#define NPAD 384
#define NS 328
#define KP 72
#define KP2 136
#define RSTR 132
#define CBUF 4160        // chunk buffer floats: convx 2048 + Bs 1024 + Cs 1024 + dts 32 + dAs 32

// ---------------- device scratch ----------------
__device__ float g_zx[(size_t)NT*ZST];
__device__ float g_y [(size_t)NT*DI];
__device__ float g_Cx[(size_t)NT*NH*DS];
__device__ float g_S  [32*SEG*2048];
__device__ float g_H0 [32*SEG*2048];
__device__ float g_D  [32*SEG];
__device__ float g_dummy[32];
__device__ __nv_bfloat16 g_Wh[(size_t)NLAYER*NPAD*64];
__device__ __nv_bfloat16 g_Wl[(size_t)NLAYER*NPAD*64];
__device__ __nv_bfloat16 g_Woh[(size_t)NLAYER*64*128];
__device__ __nv_bfloat16 g_Wol[(size_t)NLAYER*64*128];

// ---------------- f32x2 packed helpers ----------------
__device__ __forceinline__ unsigned long long pk2(float lo, float hi){
    unsigned long long r; asm("mov.b64 %0,{%1,%2};" : "=l"(r) : "f"(lo), "f"(hi)); return r;
}
__device__ __forceinline__ void upk2(unsigned long long v, float& lo, float& hi){
    asm("mov.b64 {%0,%1},%2;" : "=f"(lo), "=f"(hi) : "l"(v));
}
__device__ __forceinline__ unsigned long long mul2(unsigned long long a, unsigned long long b){
    unsigned long long d; asm("mul.rn.f32x2 %0,%1,%2;" : "=l"(d) : "l"(a), "l"(b)); return d;
}
__device__ __forceinline__ unsigned long long fma2(unsigned long long a, unsigned long long b, unsigned long long c){
    unsigned long long d; asm("fma.rn.f32x2 %0,%1,%2,%3;" : "=l"(d) : "l"(a), "l"(b), "l"(c)); return d;
}

// ---------------- bf16 helpers ----------------
__device__ __forceinline__ unsigned pkbf(float x, float y){
    __nv_bfloat162 t = __floats2bfloat162_rn(x, y);
    return *(unsigned*)&t;
}
__device__ __forceinline__ float bfres(float x){
    return x - __bfloat162float(__float2bfloat16_rn(x));
}
__device__ __forceinline__ void mma16816(float* c, const unsigned* a, const unsigned* b){
    asm volatile("mma.sync.aligned.m16n8k16.row.col.f32.bf16.bf16.f32 "
                 "{%0,%1,%2,%3}, {%4,%5,%6,%7}, {%8,%9}, {%0,%1,%2,%3};"
                 : "+f"(c[0]), "+f"(c[1]), "+f"(c[2]), "+f"(c[3])
                 : "r"(a[0]), "r"(a[1]), "r"(a[2]), "r"(a[3]), "r"(b[0]), "r"(b[1]));
}

// ---------------- cp.async helpers ----------------
__device__ __forceinline__ void cpa16(void* s, const void* g){
    unsigned a = (unsigned)__cvta_generic_to_shared(s);
    asm volatile("cp.async.ca.shared.global [%0], [%1], 16;" :: "r"(a), "l"(g));
}
__device__ __forceinline__ void cpa4(void* s, const void* g){
    unsigned a = (unsigned)__cvta_generic_to_shared(s);
    asm volatile("cp.async.ca.shared.global [%0], [%1], 4;" :: "r"(a), "l"(g));
}

// ---------------- dummy (slot-shifter: keeps ncu's fixed launch-#4 slot on k_scanf) ------
__global__ void k_nop(){ if (threadIdx.x == 0 && blockIdx.x == 0) g_dummy[0] = 0.f; }

// ---------------- kernel 0: weight prep ----------------
__global__ __launch_bounds__(256) void k_prep(const float* __restrict__ Win, const float* __restrict__ Wout)
{
    int i = blockIdx.x * 256 + threadIdx.x;
    const int NW = NLAYER*NPAD*64;
    const int NO = NLAYER*64*128;
    if (i < NW){
        int l = i / (NPAD*64);
        int r = i - l*(NPAD*64);
        int n = r >> 6, k = r & 63;
        float w = (n < DPJ) ? Win[(size_t)l*DM*DPJ + k*DPJ + n] : 0.0f;
        __nv_bfloat16 hi = __float2bfloat16_rn(w);
        g_Wh[i] = hi;
        g_Wl[i] = __float2bfloat16_rn(w - __bfloat162float(hi));
    } else if (i < NW + NO){
        int j = i - NW;
        int l = j / (64*128);
        int r = j - l*(64*128);
        int n = r >> 7, k = r & 127;
        float w = Wout[(size_t)l*DI*DM + k*DM + n];
        __nv_bfloat16 hi = __float2bfloat16_rn(w);
        g_Woh[j] = hi;
        g_Wol[j] = __float2bfloat16_rn(w - __bfloat162float(hi));
    }
}

// ---------------- kernel 1: layer-0 in-projection via mma.sync ----------------
__global__ __launch_bounds__(256) void k_inproj_mma(const float* __restrict__ xin, int layer)
{
    extern __shared__ __align__(16) char sm[];
    __nv_bfloat16* Ah = (__nv_bfloat16*)sm;
    __nv_bfloat16* Al = Ah + 128*KP;
    __nv_bfloat16* Bh = Al + 128*KP;
    __nv_bfloat16* Bl = Bh + NS*KP;
    int tid = threadIdx.x;
    size_t rowBase = (size_t)blockIdx.x << 7;

    for (int i = tid; i < 128*32; i += 256){
        int m = i >> 5, kp = (i & 31) << 1;
        float2 v = *(const float2*)&xin[(rowBase + m)*DM + kp];
        *(unsigned*)&Ah[m*KP + kp] = pkbf(v.x, v.y);
        *(unsigned*)&Al[m*KP + kp] = pkbf(bfres(v.x), bfres(v.y));
    }
    {
        const unsigned long long* WhU = (const unsigned long long*)(g_Wh + (size_t)layer*NPAD*64);
        const unsigned long long* WlU = (const unsigned long long*)(g_Wl + (size_t)layer*NPAD*64);
        for (int i = tid; i < NS*16; i += 256){
            int n = i >> 4, j = (i & 15) << 2;
            *(unsigned long long*)&Bh[n*KP + j] = WhU[n*16 + (j >> 2)];
            *(unsigned long long*)&Bl[n*KP + j] = WlU[n*16 + (j >> 2)];
        }
    }
    __syncthreads();

    int w = tid >> 5, lane = tid & 31;
    int g = lane >> 2, tg = lane & 3;
    int mrow = w*16 + g;

    unsigned ah[4][4], al[4][4];
    #pragma unroll
    for (int ks = 0; ks < 4; ks++){
        int c0 = ks*16 + tg*2;
        ah[ks][0] = *(unsigned*)&Ah[mrow*KP + c0];
        ah[ks][1] = *(unsigned*)&Ah[(mrow+8)*KP + c0];
        ah[ks][2] = *(unsigned*)&Ah[mrow*KP + c0 + 8];
        ah[ks][3] = *(unsigned*)&Ah[(mrow+8)*KP + c0 + 8];
        al[ks][0] = *(unsigned*)&Al[mrow*KP + c0];
        al[ks][1] = *(unsigned*)&Al[(mrow+8)*KP + c0];
        al[ks][2] = *(unsigned*)&Al[mrow*KP + c0 + 8];
        al[ks][3] = *(unsigned*)&Al[(mrow+8)*KP + c0 + 8];
    }

    #pragma unroll 1
    for (int nt = 0; nt < 41; nt++){
        int n = nt*8 + g;
        unsigned bh[4][2], bl[4][2];
        #pragma unroll
        for (int ks = 0; ks < 4; ks++){
            int k0 = ks*16 + tg*2;
            bh[ks][0] = *(unsigned*)&Bh[n*KP + k0];
            bh[ks][1] = *(unsigned*)&Bh[n*KP + k0 + 8];
            bl[ks][0] = *(unsigned*)&Bl[n*KP + k0];
            bl[ks][1] = *(unsigned*)&Bl[n*KP + k0 + 8];
        }
        float acc[4] = {0.f, 0.f, 0.f, 0.f};
        #pragma unroll
        for (int ks = 0; ks < 4; ks++) mma16816(acc, ah[ks], bh[ks]);
        #pragma unroll
        for (int ks = 0; ks < 4; ks++) mma16816(acc, ah[ks], bl[ks]);
        #pragma unroll
        for (int ks = 0; ks < 4; ks++) mma16816(acc, al[ks], bh[ks]);
        int col = nt*8 + tg*2;
        if (col < DPJ){
            size_t r0 = rowBase + mrow;
            *(float2*)&g_zx[r0*ZST + col]       = make_float2(acc[0], acc[1]);
            *(float2*)&g_zx[(r0 + 8)*ZST + col] = make_float2(acc[2], acc[3]);
        }
    }
}

// ---------------- kernel 2: warp-specialized conv+SiLU+dt/dA + forward scan ----------------
// consumer = warps 0-3 (scan, 16 states/thread); producer = warps 4-7 (stage + conv next chunk)
__global__ __launch_bounds__(256) void k_scanf(const float* __restrict__ cw, const float* __restrict__ cb,
                                               const float* __restrict__ dtb, const float* __restrict__ Alog,
                                               const float* __restrict__ Dpw)
{
    extern __shared__ __align__(16) float sf[];
    float* raw  = sf;                     // [35][RSTR] single buffer
    float* cbuf0 = sf + 35*RSTR;          // [2][CBUF]

    int bid = blockIdx.x;
    int bh = bid >> 5, seg = bid & 31;
    int b = bh >> 1, hh = bh & 1;
    int tid = threadIdx.x;
    size_t base = (size_t)b*LL + (size_t)seg*SLEN;
    float dp = Dpw[hh];
    float Acoef = -expf(Alog[hh]);
    float dtbv = dtb[hh];

    int cch = tid & 127;
    int gch = (cch < 64) ? (hh*64 + cch) : (cch < 96 ? (128 + cch - 64) : (160 + cch - 96));
    float w0 = cw[gch*4+0], w1 = cw[gch*4+1], w2 = cw[gch*4+2], w3 = cw[gch*4+3];
    float cbv = cb[gch];

    auto stagef = [&](int t0, int myid, int stride){
        for (int i = myid; i < 1152; i += stride){
            if (i < 1120){
                int row = i >> 5, j = i & 31;
                int fo = j << 2;
                int t = t0 - 3 + row;
                if (seg == 0 && t < 0){
                    *(float4*)&raw[row*RSTR + fo] = make_float4(0.f,0.f,0.f,0.f);
                } else {
                    size_t bt = base + t;
                    int col = (fo < 64) ? (128 + hh*64 + fo) : (fo < 96 ? (256 + fo - 64) : (288 + fo - 96));
                    cpa16(&raw[row*RSTR + fo], &g_zx[bt*ZST + col]);
                }
            } else {
                int r = 3 + (i - 1120);
                size_t bt = base + t0 - 3 + r;
                cpa4(&raw[r*RSTR + 128], &g_zx[bt*ZST + 320 + hh]);
            }
        }
        asm volatile("cp.async.commit_group;");
    };

    auto convf = [&](float* cbuf, int tb, int te){
        float* outp; int ostr; int oc;
        if (cch < 64)      { outp = cbuf;        ostr = 64; oc = cch; }
        else if (cch < 96) { outp = cbuf + 2048; ostr = 32; oc = cch - 64; }
        else               { outp = cbuf + 3072; ostr = 32; oc = cch - 96; }
        for (int tt = tb; tt < te; tt++){
            float acc = cbv + w0*raw[tt*RSTR + cch] + w1*raw[(tt+1)*RSTR + cch]
                            + w2*raw[(tt+2)*RSTR + cch] + w3*raw[(tt+3)*RSTR + cch];
            outp[tt*ostr + oc] = acc / (1.0f + __expf(-acc));
        }
    };
    auto dtf = [&](float* cbuf, int myid){
        if (myid < 32){
            float rdt = raw[(3+myid)*RSTR + 128] + dtbv;
            float dt = (rdt > 20.f) ? rdt : log1pf(expf(rdt));
            cbuf[4096 + myid] = dt;
            cbuf[4128 + myid] = expf(dt * Acoef);
        }
    };

    // prologue: all 256 threads stage+conv chunk 0 into cbuf0
    stagef(0, tid, 256);
    asm volatile("cp.async.wait_group 0;");
    __syncthreads();
    {
        int half = tid >> 7;
        convf(cbuf0, half*16, half*16 + 16);
        dtf(cbuf0, tid);
    }
    __syncthreads();

    unsigned long long hs2[8];
    #pragma unroll
    for (int i = 0; i < 8; i++) hs2[i] = pk2(0.f, 0.f);
    float dprod = 1.f;
    int p = tid >> 1, q = tid & 1;

    for (int c0 = 0; c0 < SLEN/CH; c0++){
        float* cc = cbuf0 + (c0 & 1)*CBUF;
        if (tid < 128){
            float* convx = cc;
            float* Bs = cc + 2048;
            float* Cs = cc + 3072;
            float* dts_ = cc + 4096;
            float* dAs_ = cc + 4128;
            #pragma unroll 4
            for (int s = 0; s < CH; s++){
                float dAv = dAs_[s], dtv = dts_[s];
                float x = convx[s*64 + p];
                dprod *= dAv;
                float dx = dtv * x;
                unsigned long long dx2 = pk2(dx,dx), dA2 = pk2(dAv,dAv);
                const ulonglong2* bp = (const ulonglong2*)&Bs[s*32 + (q<<4)];
                ulonglong2 b0 = bp[0], b1 = bp[1], b2 = bp[2], b3 = bp[3];
                hs2[0] = fma2(hs2[0], dA2, mul2(dx2, b0.x));
                hs2[1] = fma2(hs2[1], dA2, mul2(dx2, b0.y));
                hs2[2] = fma2(hs2[2], dA2, mul2(dx2, b1.x));
                hs2[3] = fma2(hs2[3], dA2, mul2(dx2, b1.y));
                hs2[4] = fma2(hs2[4], dA2, mul2(dx2, b2.x));
                hs2[5] = fma2(hs2[5], dA2, mul2(dx2, b2.y));
                hs2[6] = fma2(hs2[6], dA2, mul2(dx2, b3.x));
                hs2[7] = fma2(hs2[7], dA2, mul2(dx2, b3.y));
                const ulonglong2* cp = (const ulonglong2*)&Cs[s*32 + (q<<4)];
                ulonglong2 cv0 = cp[0], cv1 = cp[1], cv2 = cp[2], cv3 = cp[3];
                unsigned long long a2 = mul2(hs2[0], cv0.x);
                a2 = fma2(hs2[1], cv0.y, a2);
                a2 = fma2(hs2[2], cv1.x, a2);
                a2 = fma2(hs2[3], cv1.y, a2);
                a2 = fma2(hs2[4], cv2.x, a2);
                a2 = fma2(hs2[5], cv2.y, a2);
                a2 = fma2(hs2[6], cv3.x, a2);
                a2 = fma2(hs2[7], cv3.y, a2);
                float alo, ahi; upk2(a2, alo, ahi);
                float acc = alo + ahi;
                acc += __shfl_xor_sync(0xffffffffu, acc, 1);
                if (q == 0){
                    size_t gt = base + c0*CH + s;
                    g_y[gt*DI + hh*HD + p] = acc + dp * x;
                    if (p < 32) g_Cx[gt*(NH*DS) + hh*DS + p] = dprod * Cs[s*32 + p];
                }
            }
        } else if (c0 + 1 < SLEN/CH){
            int ptid = tid - 128;
            stagef((c0+1)*CH, ptid, 128);
            asm volatile("cp.async.wait_group 0;");
            asm volatile("bar.sync 1, 128;" ::: "memory");   // all producer groups complete & visible
            float* nb = cbuf0 + ((c0+1) & 1)*CBUF;
            convf(nb, 0, 32);
            dtf(nb, ptid);
        }
        __syncthreads();
    }

    if (tid < 128){
        float h[16];
        #pragma unroll
        for (int i = 0; i < 8; i++) upk2(hs2[i], h[2*i], h[2*i+1]);
        float* sp = &g_S[((size_t)bh*SEG + seg)*2048 + (p<<5) + (q<<4)];
        #pragma unroll
        for (int j = 0; j < 4; j++)
            *(float4*)&sp[j*4] = make_float4(h[j*4], h[j*4+1], h[j*4+2], h[j*4+3]);
        if (tid == 0) g_D[bh*SEG + seg] = dprod;
    }
}

// ---------------- kernel 2b: h0 prefix over segments (per bh), depth-4 prefetch ----------------
__global__ __launch_bounds__(64) void k_hpre()
{
    __shared__ float Dsm[SEG];
    int bh = blockIdx.x >> 3, chunk = blockIdx.x & 7;
    int e0 = chunk*256 + threadIdx.x*4;
    if (threadIdx.x < SEG) Dsm[threadIdx.x] = g_D[bh*SEG + threadIdx.x];
    __syncthreads();
    const float* Sb = &g_S[(size_t)bh*SEG*2048 + e0];
    float*       Hb = &g_H0[(size_t)bh*SEG*2048 + e0];
    float4 buf[4];
    #pragma unroll
    for (int k = 0; k < 4; k++) buf[k] = *(const float4*)(Sb + (size_t)k*2048);
    float4 h = make_float4(0.f,0.f,0.f,0.f);
    #pragma unroll 4
    for (int s = 1; s < SEG; s++){
        float4 Sv = buf[(s-1)&3];
        if (s + 3 < SEG) buf[(s-1)&3] = *(const float4*)(Sb + (size_t)(s+3)*2048);
        float D = Dsm[s-1];
        h.x = D*h.x + Sv.x; h.y = D*h.y + Sv.y;
        h.z = D*h.z + Sv.z; h.w = D*h.w + Sv.w;
        *(float4*)(Hb + (size_t)s*2048) = h;
    }
}

// ---------------- kernel 3: cross-segment correction  y += Ccum @ h0^T ----------------
__global__ __launch_bounds__(256) void k_corr()
{
    __shared__ __align__(16) float Ccums[128*32];
    __shared__ __align__(16) float h0p[2048];
    __shared__ __align__(16) float h0sm[32*68];
    int bid = blockIdx.x;
    int bh = bid >> 5, seg = bid & 31;
    if (seg == 0) return;
    int b = bh >> 1, hh = bh & 1;
    int tid = threadIdx.x;
    size_t base = (size_t)b*LL + (size_t)seg*SLEN;

    {
        const float* src = &g_Cx[base*(NH*DS) + hh*DS];
        for (int i = tid; i < 1024; i += 256){
            int t = i >> 3, j = i & 7;
            cpa16(&Ccums[t*32 + j*4], src + (size_t)t*(NH*DS) + j*4);
        }
        const float* hsrc = &g_H0[((size_t)bh*SEG + seg)*2048];
        for (int i = tid; i < 512; i += 256)
            cpa16(&h0p[i*4], hsrc + i*4);
        asm volatile("cp.async.commit_group;");
    }
    asm volatile("cp.async.wait_group 0;");
    __syncthreads();

    {
        int e = tid*8;
        float4 a = *(float4*)&h0p[e], c = *(float4*)&h0p[e+4];
        int p = e >> 5, n0 = e & 31;
        h0sm[(n0+0)*68 + p] = a.x; h0sm[(n0+1)*68 + p] = a.y;
        h0sm[(n0+2)*68 + p] = a.z; h0sm[(n0+3)*68 + p] = a.w;
        h0sm[(n0+4)*68 + p] = c.x; h0sm[(n0+5)*68 + p] = c.y;
        h0sm[(n0+6)*68 + p] = c.z; h0sm[(n0+7)*68 + p] = c.w;
    }
    __syncthreads();

    int t0 = (tid >> 3) << 2;
    int p0 = (tid & 7) << 3;
    unsigned long long acc2[4][4];
    #pragma unroll
    for (int i = 0; i < 4; i++)
        #pragma unroll
        for (int j = 0; j < 4; j++) acc2[i][j] = pk2(0.f, 0.f);
    #pragma unroll 4
    for (int n = 0; n < 32; n++){
        const ulonglong2* hp = (const ulonglong2*)&h0sm[n*68 + p0];
        ulonglong2 ha = hp[0], hb = hp[1];
        #pragma unroll
        for (int i = 0; i < 4; i++){
            float cc = Ccums[(t0+i)*32 + n];
            unsigned long long c2 = pk2(cc, cc);
            acc2[i][0] = fma2(c2, ha.x, acc2[i][0]);
            acc2[i][1] = fma2(c2, ha.y, acc2[i][1]);
            acc2[i][2] = fma2(c2, hb.x, acc2[i][2]);
            acc2[i][3] = fma2(c2, hb.y, acc2[i][3]);
        }
    }
    #pragma unroll
    for (int i = 0; i < 4; i++){
        size_t gt = base + t0 + i;
        float* yp = &g_y[gt*DI + hh*HD + p0];
        float4 y0 = *(float4*)yp, y1 = *(float4*)(yp + 4);
        float a0, a1;
        upk2(acc2[i][0], a0, a1); y0.x += a0; y0.y += a1;
        upk2(acc2[i][1], a0, a1); y0.z += a0; y0.w += a1;
        upk2(acc2[i][2], a0, a1); y1.x += a0; y1.y += a1;
        upk2(acc2[i][3], a0, a1); y1.z += a0; y1.w += a1;
        *(float4*)yp = y0; *(float4*)(yp + 4) = y1;
    }
}

// ---------------- kernel 4: fused gate+RMSnorm + outGEMM + next inGEMM ----------------
__global__ __launch_bounds__(256) void k_fused(const float* __restrict__ nw, int l)
{
    extern __shared__ __align__(16) char sm[];
    __nv_bfloat16* Yh  = (__nv_bfloat16*)sm;
    __nv_bfloat16* Yl  = Yh + 128*KP2;
    __nv_bfloat16* Wh2 = Yl + 128*KP2;
    __nv_bfloat16* Wl2 = Wh2 + 64*KP2;
    __nv_bfloat16* Hh  = (__nv_bfloat16*)sm;
    __nv_bfloat16* Hl  = Hh + 128*KP;
    __nv_bfloat16* Bh  = Hl + 128*KP;
    __nv_bfloat16* Bl  = Bh + NS*KP;

    int tid = threadIdx.x;
    size_t rowBase = (size_t)blockIdx.x << 7;

    {
        const unsigned long long* WhU = (const unsigned long long*)(g_Woh + (size_t)l*64*128);
        const unsigned long long* WlU = (const unsigned long long*)(g_Wol + (size_t)l*64*128);
        for (int i = tid; i < 64*32; i += 256){
            int n = i >> 5, j = (i & 31) << 2;
            *(unsigned long long*)&Wh2[n*KP2 + j] = WhU[i];
            *(unsigned long long*)&Wl2[n*KP2 + j] = WlU[i];
        }
    }
    #pragma unroll
    for (int hm = 0; hm < 2; hm++){
        int r = (tid >> 2) + hm*64;
        int q = tid & 3;
        int k0 = q * 32;
        size_t bt = rowBase + r;
        float v[32]; float ssq = 0.f;
        const float4* yp = (const float4*)&g_y[bt*DI + k0];
        const float2* zp = (const float2*)&g_zx[bt*ZST + k0];
        #pragma unroll
        for (int j = 0; j < 8; j++){
            float4 y4 = yp[j];
            float2 z0 = zp[2*j], z1 = zp[2*j+1];
            float g0 = z0.x / (1.0f + __expf(-z0.x));
            float g1 = z0.y / (1.0f + __expf(-z0.y));
            float g2 = z1.x / (1.0f + __expf(-z1.x));
            float g3 = z1.y / (1.0f + __expf(-z1.y));
            v[4*j+0] = y4.x * g0; v[4*j+1] = y4.y * g1;
            v[4*j+2] = y4.z * g2; v[4*j+3] = y4.w * g3;
            ssq += v[4*j]*v[4*j] + v[4*j+1]*v[4*j+1] + v[4*j+2]*v[4*j+2] + v[4*j+3]*v[4*j+3];
        }
        ssq += __shfl_xor_sync(0xffffffffu, ssq, 1);
        ssq += __shfl_xor_sync(0xffffffffu, ssq, 2);
        float rs = rsqrtf(ssq * (1.0f/128.0f) + 1e-5f);
        #pragma unroll
        for (int j = 0; j < 32; j += 2){
            float s0 = v[j]   * rs * nw[k0 + j];
            float s1 = v[j+1] * rs * nw[k0 + j + 1];
            *(unsigned*)&Yh[r*KP2 + k0 + j] = pkbf(s0, s1);
            *(unsigned*)&Yl[r*KP2 + k0 + j] = pkbf(bfres(s0), bfres(s1));
        }
    }
    __syncthreads();

    int w = tid >> 5, lane = tid & 31;
    int g = lane >> 2, tg = lane & 3;
    int mrow = w*16 + g;

    float acc1[8][4];
    #pragma unroll
    for (int nt = 0; nt < 8; nt++){
        acc1[nt][0]=0.f; acc1[nt][1]=0.f; acc1[nt][2]=0.f; acc1[nt][3]=0.f;
    }
    #pragma unroll 1
    for (int ks = 0; ks < 8; ks++){
        int c0 = ks*16 + tg*2;
        unsigned ah[4], al[4];
        ah[0] = *(unsigned*)&Yh[mrow*KP2 + c0];
        ah[1] = *(unsigned*)&Yh[(mrow+8)*KP2 + c0];
        ah[2] = *(unsigned*)&Yh[mrow*KP2 + c0 + 8];
        ah[3] = *(unsigned*)&Yh[(mrow+8)*KP2 + c0 + 8];
        al[0] = *(unsigned*)&Yl[mrow*KP2 + c0];
        al[1] = *(unsigned*)&Yl[(mrow+8)*KP2 + c0];
        al[2] = *(unsigned*)&Yl[mrow*KP2 + c0 + 8];
        al[3] = *(unsigned*)&Yl[(mrow+8)*KP2 + c0 + 8];
        #pragma unroll
        for (int nt = 0; nt < 8; nt++){
            int n = nt*8 + g;
            unsigned bh[2], bl[2];
            bh[0] = *(unsigned*)&Wh2[n*KP2 + c0];
            bh[1] = *(unsigned*)&Wh2[n*KP2 + c0 + 8];
            bl[0] = *(unsigned*)&Wl2[n*KP2 + c0];
            bl[1] = *(unsigned*)&Wl2[n*KP2 + c0 + 8];
            mma16816(acc1[nt], ah, bh);
            mma16816(acc1[nt], ah, bl);
            mma16816(acc1[nt], al, bh);
        }
    }
    __syncthreads();

    {
        const char* srcH = (const char*)(g_Wh + (size_t)(l+1)*NPAD*64);
        const char* srcL = (const char*)(g_Wl + (size_t)(l+1)*NPAD*64);
        for (int i = tid; i < NS*8; i += 256){
            int n = i >> 3, j = (i & 7) << 3;
            cpa16(&Bh[n*KP + j], srcH + (n*64 + j)*2);
            cpa16(&Bl[n*KP + j], srcL + (n*64 + j)*2);
        }
        asm volatile("cp.async.commit_group;");
    }
    #pragma unroll
    for (int nt = 0; nt < 8; nt++){
        int col = nt*8 + tg*2;
        *(unsigned*)&Hh[mrow*KP + col]     = pkbf(acc1[nt][0], acc1[nt][1]);
        *(unsigned*)&Hl[mrow*KP + col]     = pkbf(bfres(acc1[nt][0]), bfres(acc1[nt][1]));
        *(unsigned*)&Hh[(mrow+8)*KP + col] = pkbf(acc1[nt][2], acc1[nt][3]);
        *(unsigned*)&Hl[(mrow+8)*KP + col] = pkbf(bfres(acc1[nt][2]), bfres(acc1[nt][3]));
    }
    asm volatile("cp.async.wait_group 0;");
    __syncthreads();

    unsigned ah[4][4], al[4][4];
    #pragma unroll
    for (int ks = 0; ks < 4; ks++){
        int c0 = ks*16 + tg*2;
        ah[ks][0] = *(unsigned*)&Hh[mrow*KP + c0];
        ah[ks][1] = *(unsigned*)&Hh[(mrow+8)*KP + c0];
        ah[ks][2] = *(unsigned*)&Hh[mrow*KP + c0 + 8];
        ah[ks][3] = *(unsigned*)&Hh[(mrow+8)*KP + c0 + 8];
        al[ks][0] = *(unsigned*)&Hl[mrow*KP + c0];
        al[ks][1] = *(unsigned*)&Hl[(mrow+8)*KP + c0];
        al[ks][2] = *(unsigned*)&Hl[mrow*KP + c0 + 8];
        al[ks][3] = *(unsigned*)&Hl[(mrow+8)*KP + c0 + 8];
    }
    #pragma unroll 1
    for (int nt = 0; nt < 41; nt++){
        int n = nt*8 + g;
        unsigned bh[4][2], bl[4][2];
        #pragma unroll
        for (int ks = 0; ks < 4; ks++){
            int k0 = ks*16 + tg*2;
            bh[ks][0] = *(unsigned*)&Bh[n*KP + k0];
            bh[ks][1] = *(unsigned*)&Bh[n*KP + k0 + 8];
            bl[ks][0] = *(unsigned*)&Bl[n*KP + k0];
            bl[ks][1] = *(unsigned*)&Bl[n*KP + k0 + 8];
        }
        float acc[4] = {0.f, 0.f, 0.f, 0.f};
        #pragma unroll
        for (int ks = 0; ks < 4; ks++) mma16816(acc, ah[ks], bh[ks]);
        #pragma unroll
        for (int ks = 0; ks < 4; ks++) mma16816(acc, ah[ks], bl[ks]);
        #pragma unroll
        for (int ks = 0; ks < 4; ks++) mma16816(acc, al[ks], bh[ks]);
        int col = nt*8 + tg*2;
        if (col < DPJ){
            size_t r0 = rowBase + mrow;
            *(float2*)&g_zx[r0*ZST + col]       = make_float2(acc[0], acc[1]);
            *(float2*)&g_zx[(r0 + 8)*ZST + col] = make_float2(acc[2], acc[3]);
        }
    }
}

// ---------------- kernel 5: final-layer gate + RMSnorm + out-projection ----------------
__global__ __launch_bounds__(256) void k_out(const float* __restrict__ Wo, const float* __restrict__ nw,
                                             float* __restrict__ dout)
{
    extern __shared__ float dynsm[];
    float (*Yt)[72]  = (float(*)[72])dynsm;
    float (*Wsm)[64] = (float(*)[64])(dynsm + 128*72);
    int btBase = blockIdx.x << 6;
    int tid = threadIdx.x;
    {
        const float4* src = (const float4*)Wo;
        float4* dst = (float4*)&Wsm[0][0];
        #pragma unroll
        for (int i=0;i<8;i++) dst[tid + i*256] = src[tid + i*256];
    }
    {
        int r = tid >> 2, qq = tid & 3;
        size_t bt = (size_t)btBase + r;
        int k0 = qq * 32;
        float v[32]; float ssq = 0.f;
        const float4* yp = (const float4*)&g_y[bt*DI + k0];
        const float2* zp = (const float2*)&g_zx[bt*ZST + k0];
        #pragma unroll
        for (int j = 0; j < 8; j++){
            float4 y4 = yp[j];
            float2 z0 = zp[2*j], z1 = zp[2*j+1];
            float g0 = z0.x / (1.0f + __expf(-z0.x));
            float g1 = z0.y / (1.0f + __expf(-z0.y));
            float g2 = z1.x / (1.0f + __expf(-z1.x));
            float g3 = z1.y / (1.0f + __expf(-z1.y));
            v[4*j+0] = y4.x * g0; v[4*j+1] = y4.y * g1;
            v[4*j+2] = y4.z * g2; v[4*j+3] = y4.w * g3;
            ssq += v[4*j]*v[4*j] + v[4*j+1]*v[4*j+1] + v[4*j+2]*v[4*j+2] + v[4*j+3]*v[4*j+3];
        }
        ssq += __shfl_xor_sync(0xffffffffu, ssq, 1);
        ssq += __shfl_xor_sync(0xffffffffu, ssq, 2);
        float rs = rsqrtf(ssq * (1.0f/128.0f) + 1e-5f);
        #pragma unroll
        for (int j = 0; j < 32; j++)
            Yt[k0 + j][r] = v[j] * rs * nw[k0 + j];
    }
    __syncthreads();
    int tx = tid & 15, ty = tid >> 4;
    float acc[4][4];
    #pragma unroll
    for (int i=0;i<4;i++)
      #pragma unroll
      for (int j=0;j<4;j++) acc[i][j]=0.f;
    #pragma unroll 4
    for (int k=0;k<128;k++){
        float4 bv = *(const float4*)&Wsm[k][tx<<2];
        float4 av = *(const float4*)&Yt[k][ty<<2];
        acc[0][0]+=av.x*bv.x; acc[0][1]+=av.x*bv.y; acc[0][2]+=av.x*bv.z; acc[0][3]+=av.x*bv.w;
        acc[1][0]+=av.y*bv.x; acc[1][1]+=av.y*bv.y; acc[1][2]+=av.y*bv.z; acc[1][3]+=av.y*bv.w;
        acc[2][0]+=av.z*bv.x; acc[2][1]+=av.z*bv.y; acc[2][2]+=av.z*bv.z; acc[2][3]+=av.z*bv.w;
        acc[3][0]+=av.w*bv.x; acc[3][1]+=av.w*bv.y; acc[3][2]+=av.w*bv.z; acc[3][3]+=av.w*bv.w;
    }
    #pragma unroll
    for (int i=0;i<4;i++){
        size_t row = (size_t)btBase + (ty<<2) + i;
        *(float4*)&dout[row*DM + (tx<<2)] = make_float4(acc[i][0],acc[i][1],acc[i][2],acc[i][3]);
    }
}

// ---------------- launcher ----------------
extern "C" void kernel_launch(void* const* d_in, const int* in_sizes, int n_in,
                              void* d_out, int out_size)
{
    const float* x       = (const float*)d_in[0];
    const float* Win     = (const float*)d_in[1];
    const float* conv_w  = (const float*)d_in[2];
    const float* conv_b  = (const float*)d_in[3];
    const float* dt_bias = (const float*)d_in[4];
    const float* A_log   = (const float*)d_in[5];
    const float* Dpw     = (const float*)d_in[6];
    const float* norm_w  = (const float*)d_in[7];
    const float* Wout    = (const float*)d_in[8];
    (void)in_sizes; (void)n_in; (void)out_size;

    int in_smem    = (128*KP + NS*KP) * 2 * 2;
    int fused_smem = (128*KP + NS*KP) * 2 * 2;
    int scanf_smem = (35*RSTR + 2*CBUF) * 4;   // 51,760
    int out_smem   = (128*72 + 128*64)*4;
    cudaFuncSetAttribute(k_inproj_mma, cudaFuncAttributeMaxDynamicSharedMemorySize, in_smem);
    cudaFuncSetAttribute(k_fused, cudaFuncAttributeMaxDynamicSharedMemorySize, fused_smem);
    cudaFuncSetAttribute(k_scanf, cudaFuncAttributeMaxDynamicSharedMemorySize, scanf_smem);
    cudaFuncSetAttribute(k_out, cudaFuncAttributeMaxDynamicSharedMemorySize, out_smem);

    int prep_elems = NLAYER*NPAD*64 + NLAYER*64*128;
    k_prep<<<(prep_elems + 255)/256, 256>>>(Win, Wout);       // launch 1
    k_inproj_mma<<<512,256,in_smem>>>(x, 0);                  // launch 2
    k_nop<<<1,32>>>();                                        // launch 3 (slot shifter)

    for (int l = 0; l < NLAYER; l++){
        k_scanf<<<32*SEG,256,scanf_smem>>>(conv_w + l*CDIM*4, conv_b + l*CDIM,
                                           dt_bias + l*NH, A_log + l*NH, Dpw + l*NH);  // launch 4 on l=0
        k_hpre <<<32*8,64>>>();
        k_corr <<<32*SEG,256>>>();
        if (l < NLAYER-1)
            k_fused<<<512,256,fused_smem>>>(norm_w + l*DI, l);
        else
            k_out  <<<NT/64,256,out_smem>>>(Wout + (size_t)l*DI*DM, norm_w + l*DI, (float*)d_out);
    }
}